// round 5
// baseline (speedup 1.0000x reference)
#include <cuda_runtime.h>
#include <math.h>
#include <stdint.h>

// Problem constants
#define S_TOK 2048
#define C_DIM 1024
#define E_NUM 16
#define H_DIM 256
#define HS_DIM 2048
#define CAP   2048

#define BKP  20   // gateup smem K stride (BK=16 + pad), conflict-free frags
#define BKP2 36   // down smem K stride (BK=32 + pad), conflict-free frags

// ---------------------------------------------------------------------------
// Device scratch
// ---------------------------------------------------------------------------
__device__ int   g_counts[E_NUM];
__device__ int   g_elist[E_NUM * CAP];
__device__ float g_wlist[E_NUM * CAP];
__device__ int   g_tok_e[S_TOK * 4];
__device__ int   g_tok_pos[S_TOK * 4];
__device__ float g_hidden[(size_t)E_NUM * CAP * H_DIM];
__device__ float g_dout[(size_t)E_NUM * CAP * C_DIM];
__device__ float g_hs[(size_t)S_TOK * HS_DIM];
__device__ float g_gate_t[(size_t)E_NUM * H_DIM * C_DIM];   // [e][H][C] K-major
__device__ float g_up_t[(size_t)E_NUM * H_DIM * C_DIM];
__device__ float g_down_t[(size_t)E_NUM * C_DIM * H_DIM];   // [e][C][H] K-major

// ---------------------------------------------------------------------------
// Helpers
// ---------------------------------------------------------------------------
__device__ __forceinline__ uint32_t smem_u32(const void* p) {
    uint32_t a;
    asm("{ .reg .u64 t; cvta.to.shared.u64 t, %1; cvt.u32.u64 %0, t; }" : "=r"(a) : "l"(p));
    return a;
}
__device__ __forceinline__ uint32_t f2tf32(float f) {
    uint32_t r;
    asm("cvt.rna.tf32.f32 %0, %1;" : "=r"(r) : "f"(f));
    return r;
}
__device__ __forceinline__ void sts128(uint32_t a, uint32_t x, uint32_t y, uint32_t z, uint32_t w) {
    asm volatile("st.shared.v4.b32 [%0], {%1,%2,%3,%4};" :: "r"(a), "r"(x), "r"(y), "r"(z), "r"(w));
}
__device__ __forceinline__ void sts128f(uint32_t a, float4 v) {
    sts128(a, f2tf32(v.x), f2tf32(v.y), f2tf32(v.z), f2tf32(v.w));
}
__device__ __forceinline__ void mma8(float* d, const uint32_t* a, const uint32_t* b) {
    asm volatile(
        "mma.sync.aligned.m16n8k8.row.col.f32.tf32.tf32.f32 "
        "{%0,%1,%2,%3}, {%4,%5,%6,%7}, {%8,%9}, {%0,%1,%2,%3};"
        : "+f"(d[0]), "+f"(d[1]), "+f"(d[2]), "+f"(d[3])
        : "r"(a[0]), "r"(a[1]), "r"(a[2]), "r"(a[3]), "r"(b[0]), "r"(b[1]));
}
template <int STRIDE>
__device__ __forceinline__ void ld_afrag(uint32_t* a, const uint32_t* As, int row, int ks, int thr) {
    const uint32_t* p = As + row * STRIDE + ks + thr;
    a[0] = p[0];
    a[1] = p[8 * STRIDE];
    a[2] = p[4];
    a[3] = p[8 * STRIDE + 4];
}
template <int STRIDE>
__device__ __forceinline__ void ld_bfrag(uint32_t* b, const uint32_t* Bs, int n, int ks, int thr) {
    const uint32_t* p = Bs + n * STRIDE + ks + thr;
    b[0] = p[0];
    b[1] = p[4];
}

// ---------------------------------------------------------------------------
// Router: warp per token, grouped sigmoid top-k, gathered per-expert lists
// ---------------------------------------------------------------------------
__global__ void router_kernel(const float* __restrict__ x,
                              const float* __restrict__ rw,
                              const float* __restrict__ bias,
                              int* __restrict__ counts, int* __restrict__ elist,
                              float* __restrict__ wlist, int* __restrict__ tok_e,
                              int* __restrict__ tok_pos) {
    int warp_id = (int)((blockIdx.x * blockDim.x + threadIdx.x) >> 5);
    int lane = threadIdx.x & 31;
    if (warp_id >= S_TOK) return;
    const float* xr = x + (size_t)warp_id * C_DIM;
    float logits[E_NUM];
#pragma unroll
    for (int e = 0; e < E_NUM; e++) {
        const float* wr = rw + (size_t)e * C_DIM;
        float p = 0.f;
        for (int c = lane; c < C_DIM; c += 32) p = fmaf(xr[c], wr[c], p);
#pragma unroll
        for (int off = 16; off; off >>= 1) p += __shfl_xor_sync(0xffffffffu, p, off);
        logits[e] = p;
    }
    if (lane == 0) {
        float sc[E_NUM], sb[E_NUM];
#pragma unroll
        for (int e = 0; e < E_NUM; e++) {
            sc[e] = 1.f / (1.f + expf(-logits[e]));
            sb[e] = sc[e] + bias[e];
        }
        float gsc[4];
#pragma unroll
        for (int g = 0; g < 4; g++) {
            float m1 = -1e30f, m2 = -1e30f;
#pragma unroll
            for (int j = 0; j < 4; j++) {
                float v = sb[g * 4 + j];
                if (v > m1) { m2 = m1; m1 = v; } else if (v > m2) m2 = v;
            }
            gsc[g] = m1 + m2;
        }
        int bg0 = 0;
        for (int g = 1; g < 4; g++) if (gsc[g] > gsc[bg0]) bg0 = g;
        int bg1 = -1;
        for (int g = 0; g < 4; g++) {
            if (g == bg0) continue;
            if (bg1 < 0 || gsc[g] > gsc[bg1]) bg1 = g;
        }
        bool allowed[E_NUM];
#pragma unroll
        for (int e = 0; e < E_NUM; e++) {
            int g = e >> 2;
            allowed[e] = (g == bg0) || (g == bg1);
        }
        int idx[4];
        for (int k = 0; k < 4; k++) {
            int bi = 0; float bv = -1e30f;
            for (int e = 0; e < E_NUM; e++)
                if (allowed[e] && sb[e] > bv) { bv = sb[e]; bi = e; }
            allowed[bi] = false;
            idx[k] = bi;
        }
        float wsum = 1e-20f;
        for (int k = 0; k < 4; k++) wsum += sc[idx[k]];
        for (int k = 0; k < 4; k++) {
            int e = idx[k];
            int pos = atomicAdd(&counts[e], 1);
            elist[e * CAP + pos] = warp_id;
            wlist[e * CAP + pos] = sc[e] / wsum;
            tok_e[warp_id * 4 + k] = e;
            tok_pos[warp_id * 4 + k] = pos;
        }
    }
}

// ---------------------------------------------------------------------------
// Per-expert matrix transpose: in [z][R][C] -> out [z][C][R]
// ---------------------------------------------------------------------------
__global__ void transpose_kernel(const float* __restrict__ in, float* __restrict__ out,
                                 int R, int C) {
    __shared__ float t[32][33];
    int z = blockIdx.z;
    in += (size_t)z * R * C;
    out += (size_t)z * R * C;
    int c0 = blockIdx.x * 32, r0 = blockIdx.y * 32;
    int tx = threadIdx.x, ty = threadIdx.y;
#pragma unroll
    for (int j = 0; j < 32; j += 8)
        t[ty + j][tx] = in[(size_t)(r0 + ty + j) * C + c0 + tx];
    __syncthreads();
#pragma unroll
    for (int j = 0; j < 32; j += 8)
        out[(size_t)(c0 + ty + j) * R + r0 + tx] = t[tx][ty + j];
}

// ---------------------------------------------------------------------------
// Merged gate/up dual GEMM (routed experts + shared expert in ONE launch).
// 1D grid: bid < 512 -> routed tiles (e = bid>>5, y = (bid&31)>>1, x = bid&1)
//          bid >= 512 -> shared tiles (t = bid-512, x = t&15, y = t>>4)
// Tile 128x128(x2 gemms), BK=16, double-buffered smem, 512 threads.
// ---------------------------------------------------------------------------
#define GU_STG (128 * BKP)                  // floats per array per stage
#define GU_SMEM (6 * GU_STG * 4)            // 2 stages x 3 arrays

__global__ __launch_bounds__(512)
void gateup_all(const float* __restrict__ X,
                const float* __restrict__ gate_t, const float* __restrict__ up_t,
                const float* __restrict__ sgw, const float* __restrict__ suw,
                float* __restrict__ hidden, float* __restrict__ hs,
                const int* __restrict__ counts, const int* __restrict__ elist,
                const float* __restrict__ wlist) {
    extern __shared__ __align__(16) float sm[];
    const int Kd = C_DIM;
    const int NCH = Kd / 16;

    int bid = blockIdx.x;
    bool routed = bid < 512;
    int e = 0, cnt = 0, m0, n0;
    const float* Bg;
    const float* Bu;
    if (routed) {
        e = bid >> 5;
        int r = bid & 31;
        m0 = (r >> 1) * 128;
        n0 = (r & 1) * 128;
        cnt = counts[e];
        if (m0 >= cnt) return;
        Bg = gate_t + (size_t)e * H_DIM * C_DIM;
        Bu = up_t + (size_t)e * H_DIM * C_DIM;
    } else {
        int t = bid - 512;
        n0 = (t & 15) * 128;
        m0 = (t >> 4) * 128;
        Bg = sgw;
        Bu = suw;
    }

    int tid = threadIdx.x, wid = tid >> 5, lane = tid & 31;
    int grp = lane >> 2, thr = lane & 3;
    int wm = (wid & 3) * 32, wn = (wid >> 2) * 32;

    // loader mapping: 128 rows x 4 float4
    int lrow = tid >> 2, lvec = tid & 3;
    int atok;
    if (routed) {
        int idx = m0 + lrow;
        atok = elist[e * CAP + (idx < cnt ? idx : 0)];
    } else {
        atok = m0 + lrow;
    }
    const float* aptr = X + (size_t)atok * Kd + lvec * 4;
    const float* gptr = Bg + (size_t)(n0 + lrow) * Kd + lvec * 4;
    const float* uptr = Bu + (size_t)(n0 + lrow) * Kd + lvec * 4;

    uint32_t soff = (uint32_t)(lrow * BKP + lvec * 4) * 4;
    uint32_t base = smem_u32(sm);
    uint32_t asb[2] = {base + soff, base + GU_STG * 4 + soff};
    uint32_t gsb[2] = {base + 2 * GU_STG * 4 + soff, base + 3 * GU_STG * 4 + soff};
    uint32_t usb[2] = {base + 4 * GU_STG * 4 + soff, base + 5 * GU_STG * 4 + soff};
    const uint32_t* Au[2] = {(const uint32_t*)sm, (const uint32_t*)(sm + GU_STG)};
    const uint32_t* Gu[2] = {(const uint32_t*)(sm + 2 * GU_STG), (const uint32_t*)(sm + 3 * GU_STG)};
    const uint32_t* Uu[2] = {(const uint32_t*)(sm + 4 * GU_STG), (const uint32_t*)(sm + 5 * GU_STG)};

    float accg[2][4][4], accu[2][4][4];
#pragma unroll
    for (int i = 0; i < 2; i++)
#pragma unroll
        for (int j = 0; j < 4; j++)
#pragma unroll
            for (int v = 0; v < 4; v++) { accg[i][j][v] = 0.f; accu[i][j][v] = 0.f; }

    // prologue: chunk0 -> stage0; prefetch chunk1 into regs
    float4 ra = *(const float4*)aptr;
    float4 rg = *(const float4*)gptr;
    float4 ru = *(const float4*)uptr;
    sts128f(asb[0], ra);
    sts128f(gsb[0], rg);
    sts128f(usb[0], ru);
    ra = *(const float4*)(aptr + 16);
    rg = *(const float4*)(gptr + 16);
    ru = *(const float4*)(uptr + 16);
    __syncthreads();

    for (int i = 0; i < NCH; i++) {
        int cur = i & 1, nxt = cur ^ 1;
        if (i + 1 < NCH) {
            sts128f(asb[nxt], ra);
            sts128f(gsb[nxt], rg);
            sts128f(usb[nxt], ru);
            if (i + 2 < NCH) {
                int k0 = (i + 2) * 16;
                ra = *(const float4*)(aptr + k0);
                rg = *(const float4*)(gptr + k0);
                ru = *(const float4*)(uptr + k0);
            }
        }
#pragma unroll
        for (int ks = 0; ks < 16; ks += 8) {
            uint32_t af[2][4];
            ld_afrag<BKP>(af[0], Au[cur], wm + grp, ks, thr);
            ld_afrag<BKP>(af[1], Au[cur], wm + 16 + grp, ks, thr);
            uint32_t bg[4][2], bu[4][2];
#pragma unroll
            for (int j = 0; j < 4; j++) {
                ld_bfrag<BKP>(bg[j], Gu[cur], wn + j * 8 + grp, ks, thr);
                ld_bfrag<BKP>(bu[j], Uu[cur], wn + j * 8 + grp, ks, thr);
            }
#pragma unroll
            for (int mi = 0; mi < 2; mi++)
#pragma unroll
                for (int j = 0; j < 4; j++) {
                    mma8(accg[mi][j], af[mi], bg[j]);
                    mma8(accu[mi][j], af[mi], bu[j]);
                }
        }
        __syncthreads();
    }

    // epilogue: silu(g)*u*scale
#pragma unroll
    for (int mi = 0; mi < 2; mi++) {
#pragma unroll
        for (int half = 0; half < 2; half++) {
            int lrowl = wm + mi * 16 + grp + half * 8;
            int gidx = m0 + lrowl;
            float scale = 1.f;
            float* orow = nullptr;
            bool valid = true;
            if (routed) {
                valid = gidx < cnt;
                if (valid) {
                    scale = wlist[e * CAP + gidx];
                    orow = hidden + ((size_t)e * CAP + gidx) * H_DIM + n0;
                }
            } else {
                orow = hs + (size_t)gidx * HS_DIM + n0;
            }
            if (valid) {
#pragma unroll
                for (int j = 0; j < 4; j++) {
                    int c = wn + j * 8 + thr * 2;
                    float g0 = accg[mi][j][half * 2], g1 = accg[mi][j][half * 2 + 1];
                    float u0 = accu[mi][j][half * 2], u1 = accu[mi][j][half * 2 + 1];
                    float2 o;
                    o.x = (g0 / (1.f + expf(-g0))) * u0 * scale;
                    o.y = (g1 / (1.f + expf(-g1))) * u1 * scale;
                    *(float2*)(orow + c) = o;
                }
            }
        }
    }
}

// ---------------------------------------------------------------------------
// Merged down GEMM (routed + shared in ONE launch). BK=32, double-buffered.
// 1D grid: bid < 2048 -> routed (e = bid>>7, r = bid&127, y = r>>3, x = r&7)
//          bid >= 2048 -> shared (t = bid-2048, y = t>>3, x = t&7)
// ---------------------------------------------------------------------------
#define DN_STG (128 * BKP2)                 // floats per array per stage
#define DN_SMEM (4 * DN_STG * 4)            // 2 stages x 2 arrays

__global__ __launch_bounds__(512)
void down_all(const float* __restrict__ hidden, const float* __restrict__ down_t,
              const float* __restrict__ hs, const float* __restrict__ sdw,
              float* __restrict__ dout, float* __restrict__ out,
              const int* __restrict__ counts) {
    extern __shared__ __align__(16) float sm[];

    int bid = blockIdx.x;
    bool routed = bid < 2048;
    int e = 0, cnt = 0, m0, n0, Kd;
    const float* A;
    const float* B;
    float* Cc;
    if (routed) {
        e = bid >> 7;
        int r = bid & 127;
        m0 = (r >> 3) * 128;
        n0 = (r & 7) * 128;
        cnt = counts[e];
        if (m0 >= cnt) return;
        A = hidden + (size_t)e * CAP * H_DIM;
        B = down_t + (size_t)e * C_DIM * H_DIM;
        Cc = dout + (size_t)e * CAP * C_DIM;
        Kd = H_DIM;
    } else {
        int t = bid - 2048;
        m0 = (t >> 3) * 128;
        n0 = (t & 7) * 128;
        A = hs;
        B = sdw;
        Cc = out;
        Kd = HS_DIM;
    }
    const int NCH = Kd / 32;

    int tid = threadIdx.x, wid = tid >> 5, lane = tid & 31;
    int grp = lane >> 2, thr = lane & 3;
    int wm = (wid & 3) * 32, wn = (wid >> 2) * 32;

    // loader: 128 rows x 8 float4 per array; thread covers rows l0 and l0+64
    int l0 = tid >> 3, lvec = tid & 7;
    const float* aptr = A + (size_t)(m0 + l0) * Kd + lvec * 4;
    const float* bptr = B + (size_t)(n0 + l0) * Kd + lvec * 4;
    size_t rstep = (size_t)64 * Kd;

    uint32_t soff = (uint32_t)(l0 * BKP2 + lvec * 4) * 4;
    uint32_t soff2 = soff + 64 * BKP2 * 4;
    uint32_t base = smem_u32(sm);
    uint32_t asb[2] = {base + soff, base + DN_STG * 4 + soff};
    uint32_t asb2[2] = {base + soff2, base + DN_STG * 4 + soff2};
    uint32_t bsb[2] = {base + 2 * DN_STG * 4 + soff, base + 3 * DN_STG * 4 + soff};
    uint32_t bsb2[2] = {base + 2 * DN_STG * 4 + soff2, base + 3 * DN_STG * 4 + soff2};
    const uint32_t* Au[2] = {(const uint32_t*)sm, (const uint32_t*)(sm + DN_STG)};
    const uint32_t* Bu[2] = {(const uint32_t*)(sm + 2 * DN_STG), (const uint32_t*)(sm + 3 * DN_STG)};

    float acc[2][4][4];
#pragma unroll
    for (int i = 0; i < 2; i++)
#pragma unroll
        for (int j = 0; j < 4; j++)
#pragma unroll
            for (int v = 0; v < 4; v++) acc[i][j][v] = 0.f;

    float4 ra0 = *(const float4*)aptr;
    float4 ra1 = *(const float4*)(aptr + rstep);
    float4 rb0 = *(const float4*)bptr;
    float4 rb1 = *(const float4*)(bptr + rstep);
    sts128f(asb[0], ra0);
    sts128f(asb2[0], ra1);
    sts128f(bsb[0], rb0);
    sts128f(bsb2[0], rb1);
    if (NCH > 1) {
        ra0 = *(const float4*)(aptr + 32);
        ra1 = *(const float4*)(aptr + rstep + 32);
        rb0 = *(const float4*)(bptr + 32);
        rb1 = *(const float4*)(bptr + rstep + 32);
    }
    __syncthreads();

    for (int i = 0; i < NCH; i++) {
        int cur = i & 1, nxt = cur ^ 1;
        if (i + 1 < NCH) {
            sts128f(asb[nxt], ra0);
            sts128f(asb2[nxt], ra1);
            sts128f(bsb[nxt], rb0);
            sts128f(bsb2[nxt], rb1);
            if (i + 2 < NCH) {
                int k0 = (i + 2) * 32;
                ra0 = *(const float4*)(aptr + k0);
                ra1 = *(const float4*)(aptr + rstep + k0);
                rb0 = *(const float4*)(bptr + k0);
                rb1 = *(const float4*)(bptr + rstep + k0);
            }
        }
#pragma unroll
        for (int ks = 0; ks < 32; ks += 8) {
            uint32_t af[2][4];
            ld_afrag<BKP2>(af[0], Au[cur], wm + grp, ks, thr);
            ld_afrag<BKP2>(af[1], Au[cur], wm + 16 + grp, ks, thr);
            uint32_t bf[4][2];
#pragma unroll
            for (int j = 0; j < 4; j++)
                ld_bfrag<BKP2>(bf[j], Bu[cur], wn + j * 8 + grp, ks, thr);
#pragma unroll
            for (int mi = 0; mi < 2; mi++)
#pragma unroll
                for (int j = 0; j < 4; j++)
                    mma8(acc[mi][j], af[mi], bf[j]);
        }
        __syncthreads();
    }

#pragma unroll
    for (int mi = 0; mi < 2; mi++) {
#pragma unroll
        for (int half = 0; half < 2; half++) {
            int lrowl = wm + mi * 16 + grp + half * 8;
            int gidx = m0 + lrowl;
            bool valid = routed ? (gidx < cnt) : true;
            if (valid) {
                float* orow = Cc + (size_t)gidx * C_DIM + n0;
#pragma unroll
                for (int j = 0; j < 4; j++) {
                    int c = wn + j * 8 + thr * 2;
                    float2 o;
                    o.x = acc[mi][j][half * 2];
                    o.y = acc[mi][j][half * 2 + 1];
                    *(float2*)(orow + c) = o;
                }
            }
        }
    }
}

// ---------------------------------------------------------------------------
// Final combine: out[s] += sum_k dout[e_k][pos_k]
// ---------------------------------------------------------------------------
__global__ void combine_kernel(const int* __restrict__ tok_e,
                               const int* __restrict__ tok_pos,
                               const float* __restrict__ dout,
                               float* __restrict__ out) {
    int s = blockIdx.x;
    int c = threadIdx.x * 4;
    float4 acc = *(const float4*)(out + (size_t)s * C_DIM + c);
#pragma unroll
    for (int k = 0; k < 4; k++) {
        int e = tok_e[s * 4 + k];
        int p = tok_pos[s * 4 + k];
        float4 v = *(const float4*)(dout + ((size_t)e * CAP + p) * C_DIM + c);
        acc.x += v.x; acc.y += v.y; acc.z += v.z; acc.w += v.w;
    }
    *(float4*)(out + (size_t)s * C_DIM + c) = acc;
}

// ---------------------------------------------------------------------------
// Launch
// ---------------------------------------------------------------------------
extern "C" void kernel_launch(void* const* d_in, const int* in_sizes, int n_in,
                              void* d_out, int out_size) {
    const float* x      = (const float*)d_in[0];
    const float* rw     = (const float*)d_in[1];
    const float* bias   = (const float*)d_in[2];
    const float* gate_w = (const float*)d_in[3];
    const float* up_w   = (const float*)d_in[4];
    const float* down_w = (const float*)d_in[5];
    const float* sgw    = (const float*)d_in[6];
    const float* suw    = (const float*)d_in[7];
    const float* sdw    = (const float*)d_in[8];
    float* out = (float*)d_out;

    int *counts, *elist, *tok_e, *tok_pos;
    float *wlist, *hidden, *dout, *hs, *gate_t, *up_t, *down_t;
    cudaGetSymbolAddress((void**)&counts, g_counts);
    cudaGetSymbolAddress((void**)&elist, g_elist);
    cudaGetSymbolAddress((void**)&wlist, g_wlist);
    cudaGetSymbolAddress((void**)&tok_e, g_tok_e);
    cudaGetSymbolAddress((void**)&tok_pos, g_tok_pos);
    cudaGetSymbolAddress((void**)&hidden, g_hidden);
    cudaGetSymbolAddress((void**)&dout, g_dout);
    cudaGetSymbolAddress((void**)&hs, g_hs);
    cudaGetSymbolAddress((void**)&gate_t, g_gate_t);
    cudaGetSymbolAddress((void**)&up_t, g_up_t);
    cudaGetSymbolAddress((void**)&down_t, g_down_t);

    cudaFuncSetAttribute(gateup_all, cudaFuncAttributeMaxDynamicSharedMemorySize, GU_SMEM);
    cudaFuncSetAttribute(down_all, cudaFuncAttributeMaxDynamicSharedMemorySize, DN_SMEM);

    cudaMemsetAsync(counts, 0, E_NUM * sizeof(int));

    // Router + K-major weight transposes
    router_kernel<<<S_TOK / 4, 128>>>(x, rw, bias, counts, elist, wlist, tok_e, tok_pos);
    transpose_kernel<<<dim3(H_DIM / 32, C_DIM / 32, E_NUM), dim3(32, 8)>>>(gate_w, gate_t, C_DIM, H_DIM);
    transpose_kernel<<<dim3(H_DIM / 32, C_DIM / 32, E_NUM), dim3(32, 8)>>>(up_w, up_t, C_DIM, H_DIM);
    transpose_kernel<<<dim3(C_DIM / 32, H_DIM / 32, E_NUM), dim3(32, 8)>>>(down_w, down_t, H_DIM, C_DIM);

    // Merged gate/up (routed 512 slots + shared 256 tiles)
    gateup_all<<<768, 512, GU_SMEM>>>(x, gate_t, up_t, sgw, suw,
                                      hidden, hs, counts, elist, wlist);

    // Merged down (routed 2048 slots + shared 128 tiles)
    down_all<<<2176, 512, DN_SMEM>>>(hidden, down_t, hs, sdw, dout, out, counts);

    // Combine routed rows into out
    combine_kernel<<<S_TOK, 256>>>(tok_e, tok_pos, dout, out);
}

// round 6
// speedup vs baseline: 1.8437x; 1.8437x over previous
#include <cuda_runtime.h>
#include <cuda_fp16.h>
#include <math.h>
#include <stdint.h>

// Problem constants
#define S_TOK 2048
#define C_DIM 1024
#define E_NUM 16
#define H_DIM 256
#define HS_DIM 2048
#define CAP   2048

// ---------------------------------------------------------------------------
// Device scratch
// ---------------------------------------------------------------------------
__device__ int    g_counts[E_NUM];
__device__ int    g_elist[E_NUM * CAP];
__device__ float  g_wlist[E_NUM * CAP];
__device__ int    g_tok_e[S_TOK * 4];
__device__ int    g_tok_pos[S_TOK * 4];
__device__ float  g_dout[(size_t)E_NUM * CAP * C_DIM];       // fp32, 128 MB
__device__ __half g_xh[(size_t)S_TOK * C_DIM];               // x in fp16
__device__ __half g_gate_h[(size_t)E_NUM * H_DIM * C_DIM];   // [e][H][C] K-major fp16
__device__ __half g_up_h[(size_t)E_NUM * H_DIM * C_DIM];
__device__ __half g_down_h[(size_t)E_NUM * C_DIM * H_DIM];   // [e][C][H] K-major fp16
__device__ __half g_sgw_h[(size_t)HS_DIM * C_DIM];
__device__ __half g_suw_h[(size_t)HS_DIM * C_DIM];
__device__ __half g_sdw_h[(size_t)C_DIM * HS_DIM];
__device__ __half g_hidden_h[(size_t)E_NUM * CAP * H_DIM];   // fp16 hidden
__device__ __half g_hs_h[(size_t)S_TOK * HS_DIM];            // fp16 shared hidden

// ---------------------------------------------------------------------------
// Helpers
// ---------------------------------------------------------------------------
__device__ __forceinline__ uint32_t smem_u32(const void* p) {
    uint32_t a;
    asm("{ .reg .u64 t; cvta.to.shared.u64 t, %1; cvt.u32.u64 %0, t; }" : "=r"(a) : "l"(p));
    return a;
}
__device__ __forceinline__ void sts128(uint32_t a, uint4 v) {
    asm volatile("st.shared.v4.b32 [%0], {%1,%2,%3,%4};"
                 :: "r"(a), "r"(v.x), "r"(v.y), "r"(v.z), "r"(v.w));
}
__device__ __forceinline__ void ldsm4(uint32_t* r, uint32_t a) {
    asm volatile("ldmatrix.sync.aligned.m8n8.x4.shared.b16 {%0,%1,%2,%3}, [%4];"
                 : "=r"(r[0]), "=r"(r[1]), "=r"(r[2]), "=r"(r[3]) : "r"(a));
}
__device__ __forceinline__ void mma16(float* d, const uint32_t* a, const uint32_t* b) {
    asm volatile(
        "mma.sync.aligned.m16n8k16.row.col.f32.f16.f16.f32 "
        "{%0,%1,%2,%3}, {%4,%5,%6,%7}, {%8,%9}, {%0,%1,%2,%3};"
        : "+f"(d[0]), "+f"(d[1]), "+f"(d[2]), "+f"(d[3])
        : "r"(a[0]), "r"(a[1]), "r"(a[2]), "r"(a[3]), "r"(b[0]), "r"(b[1]));
}
// swizzled byte offset inside one 128x32-half stage (row stride 64B)
#define SWZ(row, seg) ((uint32_t)((row) * 64 + ((((seg) ^ ((row) >> 1)) & 3) << 4)))

// ---------------------------------------------------------------------------
// Router: warp per token, grouped sigmoid top-k
// ---------------------------------------------------------------------------
__global__ void router_kernel(const float* __restrict__ x,
                              const float* __restrict__ rw,
                              const float* __restrict__ bias,
                              int* __restrict__ counts, int* __restrict__ elist,
                              float* __restrict__ wlist, int* __restrict__ tok_e,
                              int* __restrict__ tok_pos) {
    int warp_id = (int)((blockIdx.x * blockDim.x + threadIdx.x) >> 5);
    int lane = threadIdx.x & 31;
    if (warp_id >= S_TOK) return;
    const float* xr = x + (size_t)warp_id * C_DIM;
    float logits[E_NUM];
#pragma unroll
    for (int e = 0; e < E_NUM; e++) {
        const float* wr = rw + (size_t)e * C_DIM;
        float p = 0.f;
        for (int c = lane; c < C_DIM; c += 32) p = fmaf(xr[c], wr[c], p);
#pragma unroll
        for (int off = 16; off; off >>= 1) p += __shfl_xor_sync(0xffffffffu, p, off);
        logits[e] = p;
    }
    if (lane == 0) {
        float sc[E_NUM], sb[E_NUM];
#pragma unroll
        for (int e = 0; e < E_NUM; e++) {
            sc[e] = 1.f / (1.f + expf(-logits[e]));
            sb[e] = sc[e] + bias[e];
        }
        float gsc[4];
#pragma unroll
        for (int g = 0; g < 4; g++) {
            float m1 = -1e30f, m2 = -1e30f;
#pragma unroll
            for (int j = 0; j < 4; j++) {
                float v = sb[g * 4 + j];
                if (v > m1) { m2 = m1; m1 = v; } else if (v > m2) m2 = v;
            }
            gsc[g] = m1 + m2;
        }
        int bg0 = 0;
        for (int g = 1; g < 4; g++) if (gsc[g] > gsc[bg0]) bg0 = g;
        int bg1 = -1;
        for (int g = 0; g < 4; g++) {
            if (g == bg0) continue;
            if (bg1 < 0 || gsc[g] > gsc[bg1]) bg1 = g;
        }
        bool allowed[E_NUM];
#pragma unroll
        for (int e = 0; e < E_NUM; e++) {
            int g = e >> 2;
            allowed[e] = (g == bg0) || (g == bg1);
        }
        int idx[4];
        for (int k = 0; k < 4; k++) {
            int bi = 0; float bv = -1e30f;
            for (int e = 0; e < E_NUM; e++)
                if (allowed[e] && sb[e] > bv) { bv = sb[e]; bi = e; }
            allowed[bi] = false;
            idx[k] = bi;
        }
        float wsum = 1e-20f;
        for (int k = 0; k < 4; k++) wsum += sc[idx[k]];
        for (int k = 0; k < 4; k++) {
            int e = idx[k];
            int pos = atomicAdd(&counts[e], 1);
            elist[e * CAP + pos] = warp_id;
            wlist[e * CAP + pos] = sc[e] / wsum;
            tok_e[warp_id * 4 + k] = e;
            tok_pos[warp_id * 4 + k] = pos;
        }
    }
}

// ---------------------------------------------------------------------------
// fp32 -> fp16 elementwise convert (n multiple of 8)
// ---------------------------------------------------------------------------
__global__ void cvt_half_kernel(const float* __restrict__ in, __half* __restrict__ out, int n) {
    int i = (blockIdx.x * blockDim.x + threadIdx.x) * 8;
    if (i >= n) return;
    float4 a = *(const float4*)(in + i);
    float4 b = *(const float4*)(in + i + 4);
    __half2 h[4];
    h[0] = __floats2half2_rn(a.x, a.y);
    h[1] = __floats2half2_rn(a.z, a.w);
    h[2] = __floats2half2_rn(b.x, b.y);
    h[3] = __floats2half2_rn(b.z, b.w);
    *(uint4*)(out + i) = *(uint4*)h;
}

// ---------------------------------------------------------------------------
// Per-expert transpose + cvt: in fp32 [z][R][C] -> out fp16 [z][C][R]
// ---------------------------------------------------------------------------
__global__ void transpose_cvt_kernel(const float* __restrict__ in, __half* __restrict__ out,
                                     int R, int C) {
    __shared__ float t[32][33];
    int z = blockIdx.z;
    in += (size_t)z * R * C;
    out += (size_t)z * R * C;
    int c0 = blockIdx.x * 32, r0 = blockIdx.y * 32;
    int tx = threadIdx.x, ty = threadIdx.y;
#pragma unroll
    for (int j = 0; j < 32; j += 8)
        t[ty + j][tx] = in[(size_t)(r0 + ty + j) * C + c0 + tx];
    __syncthreads();
#pragma unroll
    for (int j = 0; j < 32; j += 8)
        out[(size_t)(c0 + ty + j) * R + r0 + tx] = __float2half_rn(t[tx][ty + j]);
}

// ---------------------------------------------------------------------------
// Merged fp16 gate/up dual GEMM + SiLU (routed + shared in one launch).
// Tile 128x128 (x2 GEMMs), BK=32 halves, double-buffered swizzled smem.
// 512 threads, warp grid 4(m)x4(n), warp tile 32x32, mma m16n8k16.
// ---------------------------------------------------------------------------
#define GU_SMEM 49152   // 3 arrays x 2 stages x 8192 B

__global__ __launch_bounds__(512)
void gateup_all(const __half* __restrict__ xh,
                const __half* __restrict__ gate_h, const __half* __restrict__ up_h,
                const __half* __restrict__ sgw_h, const __half* __restrict__ suw_h,
                __half* __restrict__ hidden_h, __half* __restrict__ hs_h,
                const int* __restrict__ counts, const int* __restrict__ elist,
                const float* __restrict__ wlist) {
    extern __shared__ __align__(16) char sm[];
    const int Kd = C_DIM;
    const int NCH = Kd / 32;

    int bid = blockIdx.x;
    bool routed = bid < 512;
    int e = 0, cnt = 0, m0, n0;
    const __half* Bg;
    const __half* Bu;
    if (routed) {
        e = bid >> 5;
        int r = bid & 31;
        m0 = (r >> 1) * 128;
        n0 = (r & 1) * 128;
        cnt = counts[e];
        if (m0 >= cnt) return;
        Bg = gate_h + (size_t)e * H_DIM * C_DIM;
        Bu = up_h + (size_t)e * H_DIM * C_DIM;
    } else {
        int t = bid - 512;
        n0 = (t & 15) * 128;
        m0 = (t >> 4) * 128;
        Bg = sgw_h;
        Bu = suw_h;
    }

    int tid = threadIdx.x, wid = tid >> 5, lane = tid & 31;
    int grp = lane >> 2, thr = lane & 3;
    int wm = (wid & 3) * 32, wn = (wid >> 2) * 32;

    // loader: thread -> (row, seg); 16B per array per chunk
    int lrow = tid >> 2, lseg = tid & 3;
    int atok;
    if (routed) {
        int idx = m0 + lrow;
        atok = elist[e * CAP + (idx < cnt ? idx : 0)];
    } else {
        atok = m0 + lrow;
    }
    const __half* aptr = xh + (size_t)atok * Kd + lseg * 8;
    const __half* gptr = Bg + (size_t)(n0 + lrow) * Kd + lseg * 8;
    const __half* uptr = Bu + (size_t)(n0 + lrow) * Kd + lseg * 8;

    uint32_t base = smem_u32(sm);
    uint32_t so = SWZ(lrow, lseg);
    uint32_t asb[2] = {base + so, base + 8192 + so};
    uint32_t gsb[2] = {base + 16384 + so, base + 24576 + so};
    uint32_t usb[2] = {base + 32768 + so, base + 40960 + so};

    // fragment lane geometry
    int q = lane >> 3;
    int rA0 = wm + (q & 1) * 8 + (lane & 7);       // + mi*16
    int sAadd = q >> 1;
    int rB0 = wn + (q >> 1) * 8 + (lane & 7);      // + p*16
    int sBadd = q & 1;

    float accg[2][4][4], accu[2][4][4];
#pragma unroll
    for (int i = 0; i < 2; i++)
#pragma unroll
        for (int j = 0; j < 4; j++)
#pragma unroll
            for (int v = 0; v < 4; v++) { accg[i][j][v] = 0.f; accu[i][j][v] = 0.f; }

    uint4 ra = *(const uint4*)aptr;
    uint4 rg = *(const uint4*)gptr;
    uint4 ru = *(const uint4*)uptr;
    sts128(asb[0], ra);
    sts128(gsb[0], rg);
    sts128(usb[0], ru);
    ra = *(const uint4*)(aptr + 32);
    rg = *(const uint4*)(gptr + 32);
    ru = *(const uint4*)(uptr + 32);
    __syncthreads();

    for (int i = 0; i < NCH; i++) {
        int cur = i & 1, nxt = cur ^ 1;
        if (i + 1 < NCH) {
            sts128(asb[nxt], ra);
            sts128(gsb[nxt], rg);
            sts128(usb[nxt], ru);
            if (i + 2 < NCH) {
                int k0 = (i + 2) * 32;
                ra = *(const uint4*)(aptr + k0);
                rg = *(const uint4*)(gptr + k0);
                ru = *(const uint4*)(uptr + k0);
            }
        }
        uint32_t ab = base + cur * 8192;
        uint32_t gb = base + 16384 + cur * 8192;
        uint32_t ub = base + 32768 + cur * 8192;
#pragma unroll
        for (int ks = 0; ks < 2; ks++) {
            int s0 = ks * 2;
            uint32_t af[2][4], bgt[2][4], but[2][4];
            ldsm4(af[0], ab + SWZ(rA0, s0 + sAadd));
            ldsm4(af[1], ab + SWZ(rA0 + 16, s0 + sAadd));
            ldsm4(bgt[0], gb + SWZ(rB0, s0 + sBadd));
            ldsm4(bgt[1], gb + SWZ(rB0 + 16, s0 + sBadd));
            ldsm4(but[0], ub + SWZ(rB0, s0 + sBadd));
            ldsm4(but[1], ub + SWZ(rB0 + 16, s0 + sBadd));
#pragma unroll
            for (int mi = 0; mi < 2; mi++)
#pragma unroll
                for (int jj = 0; jj < 4; jj++) {
                    mma16(accg[mi][jj], af[mi], &bgt[jj >> 1][(jj & 1) * 2]);
                    mma16(accu[mi][jj], af[mi], &but[jj >> 1][(jj & 1) * 2]);
                }
        }
        __syncthreads();
    }

    // epilogue: silu(g)*u*scale -> fp16
#pragma unroll
    for (int mi = 0; mi < 2; mi++) {
#pragma unroll
        for (int half = 0; half < 2; half++) {
            int gidx = m0 + wm + mi * 16 + grp + half * 8;
            float scale = 1.f;
            __half* orow = nullptr;
            bool valid = true;
            if (routed) {
                valid = gidx < cnt;
                if (valid) {
                    scale = wlist[e * CAP + gidx];
                    orow = hidden_h + ((size_t)e * CAP + gidx) * H_DIM + n0;
                }
            } else {
                orow = hs_h + (size_t)gidx * HS_DIM + n0;
            }
            if (valid) {
#pragma unroll
                for (int j = 0; j < 4; j++) {
                    int c = wn + j * 8 + thr * 2;
                    float g0 = accg[mi][j][half * 2], g1 = accg[mi][j][half * 2 + 1];
                    float u0 = accu[mi][j][half * 2], u1 = accu[mi][j][half * 2 + 1];
                    float o0 = (g0 / (1.f + expf(-g0))) * u0 * scale;
                    float o1 = (g1 / (1.f + expf(-g1))) * u1 * scale;
                    *(__half2*)(orow + c) = __floats2half2_rn(o0, o1);
                }
            }
        }
    }
}

// ---------------------------------------------------------------------------
// Merged fp16 down GEMM (routed + shared). Same tiling. fp32 output.
// ---------------------------------------------------------------------------
#define DN_SMEM 32768   // 2 arrays x 2 stages x 8192 B

__global__ __launch_bounds__(512)
void down_all(const __half* __restrict__ hidden_h, const __half* __restrict__ down_h,
              const __half* __restrict__ hs_h, const __half* __restrict__ sdw_h,
              float* __restrict__ dout, float* __restrict__ out,
              const int* __restrict__ counts) {
    extern __shared__ __align__(16) char sm[];

    int bid = blockIdx.x;
    bool routed = bid < 2048;
    int e = 0, cnt = 0, m0, n0, Kd;
    const __half* A;
    const __half* B;
    float* Cc;
    if (routed) {
        e = bid >> 7;
        int r = bid & 127;
        m0 = (r >> 3) * 128;
        n0 = (r & 7) * 128;
        cnt = counts[e];
        if (m0 >= cnt) return;
        A = hidden_h + (size_t)e * CAP * H_DIM;
        B = down_h + (size_t)e * C_DIM * H_DIM;
        Cc = dout + (size_t)e * CAP * C_DIM;
        Kd = H_DIM;
    } else {
        int t = bid - 2048;
        m0 = (t >> 3) * 128;
        n0 = (t & 7) * 128;
        A = hs_h;
        B = sdw_h;
        Cc = out;
        Kd = HS_DIM;
    }
    const int NCH = Kd / 32;

    int tid = threadIdx.x, wid = tid >> 5, lane = tid & 31;
    int grp = lane >> 2, thr = lane & 3;
    int wm = (wid & 3) * 32, wn = (wid >> 2) * 32;

    int lrow = tid >> 2, lseg = tid & 3;
    const __half* aptr = A + (size_t)(m0 + lrow) * Kd + lseg * 8;
    const __half* bptr = B + (size_t)(n0 + lrow) * Kd + lseg * 8;

    uint32_t base = smem_u32(sm);
    uint32_t so = SWZ(lrow, lseg);
    uint32_t asb[2] = {base + so, base + 8192 + so};
    uint32_t bsb[2] = {base + 16384 + so, base + 24576 + so};

    int q = lane >> 3;
    int rA0 = wm + (q & 1) * 8 + (lane & 7);
    int sAadd = q >> 1;
    int rB0 = wn + (q >> 1) * 8 + (lane & 7);
    int sBadd = q & 1;

    float acc[2][4][4];
#pragma unroll
    for (int i = 0; i < 2; i++)
#pragma unroll
        for (int j = 0; j < 4; j++)
#pragma unroll
            for (int v = 0; v < 4; v++) acc[i][j][v] = 0.f;

    uint4 ra = *(const uint4*)aptr;
    uint4 rb = *(const uint4*)bptr;
    sts128(asb[0], ra);
    sts128(bsb[0], rb);
    if (NCH > 1) {
        ra = *(const uint4*)(aptr + 32);
        rb = *(const uint4*)(bptr + 32);
    }
    __syncthreads();

    for (int i = 0; i < NCH; i++) {
        int cur = i & 1, nxt = cur ^ 1;
        if (i + 1 < NCH) {
            sts128(asb[nxt], ra);
            sts128(bsb[nxt], rb);
            if (i + 2 < NCH) {
                int k0 = (i + 2) * 32;
                ra = *(const uint4*)(aptr + k0);
                rb = *(const uint4*)(bptr + k0);
            }
        }
        uint32_t ab = base + cur * 8192;
        uint32_t bb = base + 16384 + cur * 8192;
#pragma unroll
        for (int ks = 0; ks < 2; ks++) {
            int s0 = ks * 2;
            uint32_t af[2][4], bft[2][4];
            ldsm4(af[0], ab + SWZ(rA0, s0 + sAadd));
            ldsm4(af[1], ab + SWZ(rA0 + 16, s0 + sAadd));
            ldsm4(bft[0], bb + SWZ(rB0, s0 + sBadd));
            ldsm4(bft[1], bb + SWZ(rB0 + 16, s0 + sBadd));
#pragma unroll
            for (int mi = 0; mi < 2; mi++)
#pragma unroll
                for (int jj = 0; jj < 4; jj++)
                    mma16(acc[mi][jj], af[mi], &bft[jj >> 1][(jj & 1) * 2]);
        }
        __syncthreads();
    }

#pragma unroll
    for (int mi = 0; mi < 2; mi++) {
#pragma unroll
        for (int half = 0; half < 2; half++) {
            int gidx = m0 + wm + mi * 16 + grp + half * 8;
            bool valid = routed ? (gidx < cnt) : true;
            if (valid) {
                float* orow = Cc + (size_t)gidx * C_DIM + n0;
#pragma unroll
                for (int j = 0; j < 4; j++) {
                    int c = wn + j * 8 + thr * 2;
                    float2 o;
                    o.x = acc[mi][j][half * 2];
                    o.y = acc[mi][j][half * 2 + 1];
                    *(float2*)(orow + c) = o;
                }
            }
        }
    }
}

// ---------------------------------------------------------------------------
// Final combine: out[s] += sum_k dout[e_k][pos_k]
// ---------------------------------------------------------------------------
__global__ void combine_kernel(const int* __restrict__ tok_e,
                               const int* __restrict__ tok_pos,
                               const float* __restrict__ dout,
                               float* __restrict__ out) {
    int s = blockIdx.x;
    int c = threadIdx.x * 4;
    float4 acc = *(const float4*)(out + (size_t)s * C_DIM + c);
#pragma unroll
    for (int k = 0; k < 4; k++) {
        int e = tok_e[s * 4 + k];
        int p = tok_pos[s * 4 + k];
        float4 v = *(const float4*)(dout + ((size_t)e * CAP + p) * C_DIM + c);
        acc.x += v.x; acc.y += v.y; acc.z += v.z; acc.w += v.w;
    }
    *(float4*)(out + (size_t)s * C_DIM + c) = acc;
}

// ---------------------------------------------------------------------------
// Launch
// ---------------------------------------------------------------------------
extern "C" void kernel_launch(void* const* d_in, const int* in_sizes, int n_in,
                              void* d_out, int out_size) {
    const float* x      = (const float*)d_in[0];
    const float* rw     = (const float*)d_in[1];
    const float* bias   = (const float*)d_in[2];
    const float* gate_w = (const float*)d_in[3];
    const float* up_w   = (const float*)d_in[4];
    const float* down_w = (const float*)d_in[5];
    const float* sgw    = (const float*)d_in[6];
    const float* suw    = (const float*)d_in[7];
    const float* sdw    = (const float*)d_in[8];
    float* out = (float*)d_out;

    int *counts, *elist, *tok_e, *tok_pos;
    float *wlist, *dout;
    __half *xh, *gate_h, *up_h, *down_h, *sgw_h, *suw_h, *sdw_h, *hidden_h, *hs_h;
    cudaGetSymbolAddress((void**)&counts, g_counts);
    cudaGetSymbolAddress((void**)&elist, g_elist);
    cudaGetSymbolAddress((void**)&wlist, g_wlist);
    cudaGetSymbolAddress((void**)&tok_e, g_tok_e);
    cudaGetSymbolAddress((void**)&tok_pos, g_tok_pos);
    cudaGetSymbolAddress((void**)&dout, g_dout);
    cudaGetSymbolAddress((void**)&xh, g_xh);
    cudaGetSymbolAddress((void**)&gate_h, g_gate_h);
    cudaGetSymbolAddress((void**)&up_h, g_up_h);
    cudaGetSymbolAddress((void**)&down_h, g_down_h);
    cudaGetSymbolAddress((void**)&sgw_h, g_sgw_h);
    cudaGetSymbolAddress((void**)&suw_h, g_suw_h);
    cudaGetSymbolAddress((void**)&sdw_h, g_sdw_h);
    cudaGetSymbolAddress((void**)&hidden_h, g_hidden_h);
    cudaGetSymbolAddress((void**)&hs_h, g_hs_h);

    cudaFuncSetAttribute(gateup_all, cudaFuncAttributeMaxDynamicSharedMemorySize, GU_SMEM);
    cudaFuncSetAttribute(down_all, cudaFuncAttributeMaxDynamicSharedMemorySize, DN_SMEM);

    cudaMemsetAsync(counts, 0, E_NUM * sizeof(int));

    // Router + fp16 conversions / transposes (mutually independent)
    router_kernel<<<S_TOK / 4, 128>>>(x, rw, bias, counts, elist, wlist, tok_e, tok_pos);
    const int NELEM = S_TOK * C_DIM;  // 2M, same for sgw/suw/sdw
    cvt_half_kernel<<<NELEM / 8 / 256, 256>>>(x, xh, NELEM);
    cvt_half_kernel<<<NELEM / 8 / 256, 256>>>(sgw, sgw_h, HS_DIM * C_DIM);
    cvt_half_kernel<<<NELEM / 8 / 256, 256>>>(suw, suw_h, HS_DIM * C_DIM);
    cvt_half_kernel<<<NELEM / 8 / 256, 256>>>(sdw, sdw_h, C_DIM * HS_DIM);
    transpose_cvt_kernel<<<dim3(H_DIM / 32, C_DIM / 32, E_NUM), dim3(32, 8)>>>(gate_w, gate_h, C_DIM, H_DIM);
    transpose_cvt_kernel<<<dim3(H_DIM / 32, C_DIM / 32, E_NUM), dim3(32, 8)>>>(up_w, up_h, C_DIM, H_DIM);
    transpose_cvt_kernel<<<dim3(C_DIM / 32, H_DIM / 32, E_NUM), dim3(32, 8)>>>(down_w, down_h, H_DIM, C_DIM);

    // Merged gate/up (routed 512 slots + shared 256 tiles)
    gateup_all<<<768, 512, GU_SMEM>>>(xh, gate_h, up_h, sgw_h, suw_h,
                                      hidden_h, hs_h, counts, elist, wlist);

    // Merged down (routed 2048 slots + shared 128 tiles)
    down_all<<<2176, 512, DN_SMEM>>>(hidden_h, down_h, hs_h, sdw_h, dout, out, counts);

    // Combine routed rows into out
    combine_kernel<<<S_TOK, 256>>>(tok_e, tok_pos, dout, out);
}

// round 7
// speedup vs baseline: 1.9904x; 1.0796x over previous
#include <cuda_runtime.h>
#include <cuda_fp16.h>
#include <math.h>
#include <stdint.h>

// Problem constants
#define S_TOK 2048
#define C_DIM 1024
#define E_NUM 16
#define H_DIM 256
#define HS_DIM 2048
#define CAP   2048

// ---------------------------------------------------------------------------
// Device scratch
// ---------------------------------------------------------------------------
__device__ int    g_counts[E_NUM];
__device__ int    g_elist[E_NUM * CAP];
__device__ float  g_wlist[E_NUM * CAP];
__device__ int    g_tok_e[S_TOK * 4];
__device__ int    g_tok_pos[S_TOK * 4];
__device__ __half g_dout_h[(size_t)E_NUM * CAP * C_DIM];     // fp16, 64 MB
__device__ __half g_xh[(size_t)S_TOK * C_DIM];
__device__ __half g_gate_h[(size_t)E_NUM * H_DIM * C_DIM];   // [e][H][C] K-major
__device__ __half g_up_h[(size_t)E_NUM * H_DIM * C_DIM];
__device__ __half g_down_h[(size_t)E_NUM * C_DIM * H_DIM];   // [e][C][H] K-major
__device__ __half g_sgw_h[(size_t)HS_DIM * C_DIM];
__device__ __half g_suw_h[(size_t)HS_DIM * C_DIM];
__device__ __half g_sdw_h[(size_t)C_DIM * HS_DIM];
__device__ __half g_hidden_h[(size_t)E_NUM * CAP * H_DIM];
__device__ __half g_hs_h[(size_t)S_TOK * HS_DIM];

// ---------------------------------------------------------------------------
// Helpers
// ---------------------------------------------------------------------------
__device__ __forceinline__ uint32_t smem_u32(const void* p) {
    uint32_t a;
    asm("{ .reg .u64 t; cvta.to.shared.u64 t, %1; cvt.u32.u64 %0, t; }" : "=r"(a) : "l"(p));
    return a;
}
__device__ __forceinline__ void cpasync16(uint32_t dst, const void* src) {
    asm volatile("cp.async.cg.shared.global [%0], [%1], 16;" :: "r"(dst), "l"(src));
}
#define CP_COMMIT() asm volatile("cp.async.commit_group;" ::: "memory")
#define CP_WAIT1()  asm volatile("cp.async.wait_group 1;" ::: "memory")
#define CP_WAIT0()  asm volatile("cp.async.wait_group 0;" ::: "memory")
__device__ __forceinline__ void ldsm4(uint32_t* r, uint32_t a) {
    asm volatile("ldmatrix.sync.aligned.m8n8.x4.shared.b16 {%0,%1,%2,%3}, [%4];"
                 : "=r"(r[0]), "=r"(r[1]), "=r"(r[2]), "=r"(r[3]) : "r"(a));
}
__device__ __forceinline__ void mma16(float* d, const uint32_t* a, const uint32_t* b) {
    asm volatile(
        "mma.sync.aligned.m16n8k16.row.col.f32.f16.f16.f32 "
        "{%0,%1,%2,%3}, {%4,%5,%6,%7}, {%8,%9}, {%0,%1,%2,%3};"
        : "+f"(d[0]), "+f"(d[1]), "+f"(d[2]), "+f"(d[3])
        : "r"(a[0]), "r"(a[1]), "r"(a[2]), "r"(a[3]), "r"(b[0]), "r"(b[1]));
}
// swizzled byte offset inside one 128x32-half stage (row stride 64B)
#define SWZ(row, seg) ((uint32_t)((row) * 64 + ((((seg) ^ ((row) >> 1)) & 3) << 4)))

// ---------------------------------------------------------------------------
// Merged prep: fp16 conversions, weight transposes, router — ONE launch.
// blocks [0,4096): cvt (x, sgw, suw, sdw), 2M elems each
// blocks [4096,16384): transpose+cvt (gate, up, down)
// blocks [16384,16640): router, 8 warps/block
// ---------------------------------------------------------------------------
__global__ __launch_bounds__(256)
void prep_kernel(const float* __restrict__ x, const float* __restrict__ sgw,
                 const float* __restrict__ suw, const float* __restrict__ sdw,
                 const float* __restrict__ gate_w, const float* __restrict__ up_w,
                 const float* __restrict__ down_w,
                 const float* __restrict__ rw, const float* __restrict__ bias,
                 __half* __restrict__ xh, __half* __restrict__ sgw_h,
                 __half* __restrict__ suw_h, __half* __restrict__ sdw_h,
                 __half* __restrict__ gate_h, __half* __restrict__ up_h,
                 __half* __restrict__ down_h,
                 int* __restrict__ counts, int* __restrict__ elist,
                 float* __restrict__ wlist, int* __restrict__ tok_e,
                 int* __restrict__ tok_pos) {
    int b = blockIdx.x;
    int tid = threadIdx.x;

    if (b < 4096) {
        // ---- fp32 -> fp16 flat convert, 8 elems/thread
        const float* src;
        __half* dst;
        int lb;
        if (b < 1024)      { src = x;   dst = xh;    lb = b; }
        else if (b < 2048) { src = sgw; dst = sgw_h; lb = b - 1024; }
        else if (b < 3072) { src = suw; dst = suw_h; lb = b - 2048; }
        else               { src = sdw; dst = sdw_h; lb = b - 3072; }
        int i = (lb * 256 + tid) * 8;
        float4 a = *(const float4*)(src + i);
        float4 c = *(const float4*)(src + i + 4);
        __half2 h[4];
        h[0] = __floats2half2_rn(a.x, a.y);
        h[1] = __floats2half2_rn(a.z, a.w);
        h[2] = __floats2half2_rn(c.x, c.y);
        h[3] = __floats2half2_rn(c.z, c.w);
        *(uint4*)(dst + i) = *(uint4*)h;
    } else if (b < 16384) {
        // ---- transpose + cvt: in fp32 [z][R][C] -> out fp16 [z][C][R]
        __shared__ float t[32][33];
        int tt = b - 4096;
        const float* in;
        __half* outp;
        int R, C, bx, by, bz;
        if (tt < 4096) {
            in = gate_w; outp = gate_h; R = C_DIM; C = H_DIM;
            bz = tt >> 8; int r = tt & 255; by = r >> 3; bx = r & 7;
        } else if (tt < 8192) {
            tt -= 4096;
            in = up_w; outp = up_h; R = C_DIM; C = H_DIM;
            bz = tt >> 8; int r = tt & 255; by = r >> 3; bx = r & 7;
        } else {
            tt -= 8192;
            in = down_w; outp = down_h; R = H_DIM; C = C_DIM;
            bz = tt >> 8; int r = tt & 255; by = r >> 5; bx = r & 31;
        }
        in += (size_t)bz * R * C;
        outp += (size_t)bz * R * C;
        int c0 = bx * 32, r0 = by * 32;
        int tx = tid & 31, ty = tid >> 5;
#pragma unroll
        for (int j = 0; j < 32; j += 8)
            t[ty + j][tx] = in[(size_t)(r0 + ty + j) * C + c0 + tx];
        __syncthreads();
#pragma unroll
        for (int j = 0; j < 32; j += 8)
            outp[(size_t)(c0 + ty + j) * R + r0 + tx] = __float2half_rn(t[tx][ty + j]);
    } else {
        // ---- router: warp per token
        int warp_id = (b - 16384) * 8 + (tid >> 5);
        int lane = tid & 31;
        if (warp_id >= S_TOK) return;
        const float* xr = x + (size_t)warp_id * C_DIM;
        float logits[E_NUM];
#pragma unroll
        for (int e = 0; e < E_NUM; e++) {
            const float* wr = rw + (size_t)e * C_DIM;
            float p = 0.f;
            for (int c = lane; c < C_DIM; c += 32) p = fmaf(xr[c], wr[c], p);
#pragma unroll
            for (int off = 16; off; off >>= 1) p += __shfl_xor_sync(0xffffffffu, p, off);
            logits[e] = p;
        }
        if (lane == 0) {
            float sc[E_NUM], sb[E_NUM];
#pragma unroll
            for (int e = 0; e < E_NUM; e++) {
                sc[e] = 1.f / (1.f + expf(-logits[e]));
                sb[e] = sc[e] + bias[e];
            }
            float gsc[4];
#pragma unroll
            for (int g = 0; g < 4; g++) {
                float m1 = -1e30f, m2 = -1e30f;
#pragma unroll
                for (int j = 0; j < 4; j++) {
                    float v = sb[g * 4 + j];
                    if (v > m1) { m2 = m1; m1 = v; } else if (v > m2) m2 = v;
                }
                gsc[g] = m1 + m2;
            }
            int bg0 = 0;
            for (int g = 1; g < 4; g++) if (gsc[g] > gsc[bg0]) bg0 = g;
            int bg1 = -1;
            for (int g = 0; g < 4; g++) {
                if (g == bg0) continue;
                if (bg1 < 0 || gsc[g] > gsc[bg1]) bg1 = g;
            }
            bool allowed[E_NUM];
#pragma unroll
            for (int e = 0; e < E_NUM; e++) {
                int g = e >> 2;
                allowed[e] = (g == bg0) || (g == bg1);
            }
            int idx[4];
            for (int k = 0; k < 4; k++) {
                int bi = 0; float bv = -1e30f;
                for (int e = 0; e < E_NUM; e++)
                    if (allowed[e] && sb[e] > bv) { bv = sb[e]; bi = e; }
                allowed[bi] = false;
                idx[k] = bi;
            }
            float wsum = 1e-20f;
            for (int k = 0; k < 4; k++) wsum += sc[idx[k]];
            for (int k = 0; k < 4; k++) {
                int e = idx[k];
                int pos = atomicAdd(&counts[e], 1);
                elist[e * CAP + pos] = warp_id;
                wlist[e * CAP + pos] = sc[e] / wsum;
                tok_e[warp_id * 4 + k] = e;
                tok_pos[warp_id * 4 + k] = pos;
            }
        }
    }
}

// ---------------------------------------------------------------------------
// Merged fp16 gate/up dual GEMM + SiLU. cp.async 3-stage pipeline.
// Tile 128x128 (x2 GEMMs), BK=32 halves, 512 threads, warp tile 32x32.
// ---------------------------------------------------------------------------
#define GU_SMEM 73728   // 3 arrays x 3 stages x 8192 B

__global__ __launch_bounds__(512)
void gateup_all(const __half* __restrict__ xh,
                const __half* __restrict__ gate_h, const __half* __restrict__ up_h,
                const __half* __restrict__ sgw_h, const __half* __restrict__ suw_h,
                __half* __restrict__ hidden_h, __half* __restrict__ hs_h,
                const int* __restrict__ counts, const int* __restrict__ elist,
                const float* __restrict__ wlist) {
    extern __shared__ __align__(16) char sm[];
    const int Kd = C_DIM;
    const int NCH = Kd / 32;

    int bid = blockIdx.x;
    bool routed = bid < 512;
    int e = 0, cnt = 0, m0, n0;
    const __half* Bg;
    const __half* Bu;
    if (routed) {
        e = bid >> 5;
        int r = bid & 31;
        m0 = (r >> 1) * 128;
        n0 = (r & 1) * 128;
        cnt = counts[e];
        if (m0 >= cnt) return;
        Bg = gate_h + (size_t)e * H_DIM * C_DIM;
        Bu = up_h + (size_t)e * H_DIM * C_DIM;
    } else {
        int t = bid - 512;
        n0 = (t & 15) * 128;
        m0 = (t >> 4) * 128;
        Bg = sgw_h;
        Bu = suw_h;
    }

    int tid = threadIdx.x, wid = tid >> 5, lane = tid & 31;
    int grp = lane >> 2, thr = lane & 3;
    int wm = (wid & 3) * 32, wn = (wid >> 2) * 32;

    // loader: thread -> (row, seg); one cp.async 16B per array per chunk
    int lrow = tid >> 2, lseg = tid & 3;
    int atok;
    if (routed) {
        int idx = m0 + lrow;
        atok = elist[e * CAP + (idx < cnt ? idx : 0)];
    } else {
        atok = m0 + lrow;
    }
    const __half* aptr = xh + (size_t)atok * Kd + lseg * 8;
    const __half* gptr = Bg + (size_t)(n0 + lrow) * Kd + lseg * 8;
    const __half* uptr = Bu + (size_t)(n0 + lrow) * Kd + lseg * 8;

    uint32_t base = smem_u32(sm);
    uint32_t so = SWZ(lrow, lseg);
    uint32_t stA[3] = {base + so, base + 8192 + so, base + 16384 + so};
    uint32_t stG[3] = {base + 24576 + so, base + 32768 + so, base + 40960 + so};
    uint32_t stU[3] = {base + 49152 + so, base + 57344 + so, base + 65536 + so};

    int q = lane >> 3;
    int rA0 = wm + (q & 1) * 8 + (lane & 7);
    int sAadd = q >> 1;
    int rB0 = wn + (q >> 1) * 8 + (lane & 7);
    int sBadd = q & 1;

    float accg[2][4][4], accu[2][4][4];
#pragma unroll
    for (int i = 0; i < 2; i++)
#pragma unroll
        for (int j = 0; j < 4; j++)
#pragma unroll
            for (int v = 0; v < 4; v++) { accg[i][j][v] = 0.f; accu[i][j][v] = 0.f; }

    // prologue: issue chunks 0,1
    cpasync16(stA[0], aptr);
    cpasync16(stG[0], gptr);
    cpasync16(stU[0], uptr);
    CP_COMMIT();
    cpasync16(stA[1], aptr + 32);
    cpasync16(stG[1], gptr + 32);
    cpasync16(stU[1], uptr + 32);
    CP_COMMIT();

    for (int i = 0; i < NCH; i++) {
        if (i + 1 < NCH) CP_WAIT1(); else CP_WAIT0();
        __syncthreads();
        if (i + 2 < NCH) {
            int s = (i + 2) % 3;
            int k0 = (i + 2) * 32;
            cpasync16(stA[s], aptr + k0);
            cpasync16(stG[s], gptr + k0);
            cpasync16(stU[s], uptr + k0);
            CP_COMMIT();
        }
        int cur = i % 3;
        uint32_t ab = base + cur * 8192;
        uint32_t gb = base + 24576 + cur * 8192;
        uint32_t ub = base + 49152 + cur * 8192;
#pragma unroll
        for (int ks = 0; ks < 2; ks++) {
            int s0 = ks * 2;
            uint32_t af[2][4], bgt[2][4], but[2][4];
            ldsm4(af[0], ab + SWZ(rA0, s0 + sAadd));
            ldsm4(af[1], ab + SWZ(rA0 + 16, s0 + sAadd));
            ldsm4(bgt[0], gb + SWZ(rB0, s0 + sBadd));
            ldsm4(bgt[1], gb + SWZ(rB0 + 16, s0 + sBadd));
            ldsm4(but[0], ub + SWZ(rB0, s0 + sBadd));
            ldsm4(but[1], ub + SWZ(rB0 + 16, s0 + sBadd));
#pragma unroll
            for (int mi = 0; mi < 2; mi++)
#pragma unroll
                for (int jj = 0; jj < 4; jj++) {
                    mma16(accg[mi][jj], af[mi], &bgt[jj >> 1][(jj & 1) * 2]);
                    mma16(accu[mi][jj], af[mi], &but[jj >> 1][(jj & 1) * 2]);
                }
        }
    }

    // epilogue: silu(g)*u*scale -> fp16
#pragma unroll
    for (int mi = 0; mi < 2; mi++) {
#pragma unroll
        for (int half = 0; half < 2; half++) {
            int gidx = m0 + wm + mi * 16 + grp + half * 8;
            float scale = 1.f;
            __half* orow = nullptr;
            bool valid = true;
            if (routed) {
                valid = gidx < cnt;
                if (valid) {
                    scale = wlist[e * CAP + gidx];
                    orow = hidden_h + ((size_t)e * CAP + gidx) * H_DIM + n0;
                }
            } else {
                orow = hs_h + (size_t)gidx * HS_DIM + n0;
            }
            if (valid) {
#pragma unroll
                for (int j = 0; j < 4; j++) {
                    int c = wn + j * 8 + thr * 2;
                    float g0 = accg[mi][j][half * 2], g1 = accg[mi][j][half * 2 + 1];
                    float u0 = accu[mi][j][half * 2], u1 = accu[mi][j][half * 2 + 1];
                    float o0 = (g0 / (1.f + expf(-g0))) * u0 * scale;
                    float o1 = (g1 / (1.f + expf(-g1))) * u1 * scale;
                    *(__half2*)(orow + c) = __floats2half2_rn(o0, o1);
                }
            }
        }
    }
}

// ---------------------------------------------------------------------------
// Merged fp16 down GEMM. cp.async 3-stage pipeline. Routed -> fp16 dout,
// shared -> fp32 out.
// ---------------------------------------------------------------------------
#define DN_SMEM 49152   // 2 arrays x 3 stages x 8192 B

__global__ __launch_bounds__(512)
void down_all(const __half* __restrict__ hidden_h, const __half* __restrict__ down_h,
              const __half* __restrict__ hs_h, const __half* __restrict__ sdw_h,
              __half* __restrict__ dout_h, float* __restrict__ out,
              const int* __restrict__ counts) {
    extern __shared__ __align__(16) char sm[];

    int bid = blockIdx.x;
    bool routed = bid < 2048;
    int e = 0, cnt = 0, m0, n0, Kd;
    const __half* A;
    const __half* B;
    if (routed) {
        e = bid >> 7;
        int r = bid & 127;
        m0 = (r >> 3) * 128;
        n0 = (r & 7) * 128;
        cnt = counts[e];
        if (m0 >= cnt) return;
        A = hidden_h + (size_t)e * CAP * H_DIM;
        B = down_h + (size_t)e * C_DIM * H_DIM;
        Kd = H_DIM;
    } else {
        int t = bid - 2048;
        m0 = (t >> 3) * 128;
        n0 = (t & 7) * 128;
        A = hs_h;
        B = sdw_h;
        Kd = HS_DIM;
    }
    const int NCH = Kd / 32;

    int tid = threadIdx.x, wid = tid >> 5, lane = tid & 31;
    int grp = lane >> 2, thr = lane & 3;
    int wm = (wid & 3) * 32, wn = (wid >> 2) * 32;

    int lrow = tid >> 2, lseg = tid & 3;
    const __half* aptr = A + (size_t)(m0 + lrow) * Kd + lseg * 8;
    const __half* bptr = B + (size_t)(n0 + lrow) * Kd + lseg * 8;

    uint32_t base = smem_u32(sm);
    uint32_t so = SWZ(lrow, lseg);
    uint32_t stA[3] = {base + so, base + 8192 + so, base + 16384 + so};
    uint32_t stB[3] = {base + 24576 + so, base + 32768 + so, base + 40960 + so};

    int q = lane >> 3;
    int rA0 = wm + (q & 1) * 8 + (lane & 7);
    int sAadd = q >> 1;
    int rB0 = wn + (q >> 1) * 8 + (lane & 7);
    int sBadd = q & 1;

    float acc[2][4][4];
#pragma unroll
    for (int i = 0; i < 2; i++)
#pragma unroll
        for (int j = 0; j < 4; j++)
#pragma unroll
            for (int v = 0; v < 4; v++) acc[i][j][v] = 0.f;

    cpasync16(stA[0], aptr);
    cpasync16(stB[0], bptr);
    CP_COMMIT();
    if (NCH > 1) {
        cpasync16(stA[1], aptr + 32);
        cpasync16(stB[1], bptr + 32);
    }
    CP_COMMIT();

    for (int i = 0; i < NCH; i++) {
        if (i + 1 < NCH) CP_WAIT1(); else CP_WAIT0();
        __syncthreads();
        if (i + 2 < NCH) {
            int s = (i + 2) % 3;
            int k0 = (i + 2) * 32;
            cpasync16(stA[s], aptr + k0);
            cpasync16(stB[s], bptr + k0);
            CP_COMMIT();
        }
        int cur = i % 3;
        uint32_t ab = base + cur * 8192;
        uint32_t bb = base + 24576 + cur * 8192;
#pragma unroll
        for (int ks = 0; ks < 2; ks++) {
            int s0 = ks * 2;
            uint32_t af[2][4], bft[2][4];
            ldsm4(af[0], ab + SWZ(rA0, s0 + sAadd));
            ldsm4(af[1], ab + SWZ(rA0 + 16, s0 + sAadd));
            ldsm4(bft[0], bb + SWZ(rB0, s0 + sBadd));
            ldsm4(bft[1], bb + SWZ(rB0 + 16, s0 + sBadd));
#pragma unroll
            for (int mi = 0; mi < 2; mi++)
#pragma unroll
                for (int jj = 0; jj < 4; jj++)
                    mma16(acc[mi][jj], af[mi], &bft[jj >> 1][(jj & 1) * 2]);
        }
    }

#pragma unroll
    for (int mi = 0; mi < 2; mi++) {
#pragma unroll
        for (int half = 0; half < 2; half++) {
            int gidx = m0 + wm + mi * 16 + grp + half * 8;
            if (routed) {
                if (gidx < cnt) {
                    __half* orow = dout_h + ((size_t)e * CAP + gidx) * C_DIM + n0;
#pragma unroll
                    for (int j = 0; j < 4; j++) {
                        int c = wn + j * 8 + thr * 2;
                        *(__half2*)(orow + c) = __floats2half2_rn(acc[mi][j][half * 2],
                                                                  acc[mi][j][half * 2 + 1]);
                    }
                }
            } else {
                float* orow = out + (size_t)gidx * C_DIM + n0;
#pragma unroll
                for (int j = 0; j < 4; j++) {
                    int c = wn + j * 8 + thr * 2;
                    float2 o;
                    o.x = acc[mi][j][half * 2];
                    o.y = acc[mi][j][half * 2 + 1];
                    *(float2*)(orow + c) = o;
                }
            }
        }
    }
}

// ---------------------------------------------------------------------------
// Final combine: out[s] += sum_k dout_h[e_k][pos_k]  (fp16 gather, fp32 sum)
// ---------------------------------------------------------------------------
__global__ void combine_kernel(const int* __restrict__ tok_e,
                               const int* __restrict__ tok_pos,
                               const __half* __restrict__ dout_h,
                               float* __restrict__ out) {
    int s = blockIdx.x;
    int c = threadIdx.x * 4;
    float4 acc = *(const float4*)(out + (size_t)s * C_DIM + c);
#pragma unroll
    for (int k = 0; k < 4; k++) {
        int e = tok_e[s * 4 + k];
        int p = tok_pos[s * 4 + k];
        const __half* row = dout_h + ((size_t)e * CAP + p) * C_DIM + c;
        uint2 raw = *(const uint2*)row;
        __half2 h0 = *(__half2*)&raw.x;
        __half2 h1 = *(__half2*)&raw.y;
        float2 f0 = __half22float2(h0);
        float2 f1 = __half22float2(h1);
        acc.x += f0.x; acc.y += f0.y; acc.z += f1.x; acc.w += f1.y;
    }
    *(float4*)(out + (size_t)s * C_DIM + c) = acc;
}

// ---------------------------------------------------------------------------
// Launch
// ---------------------------------------------------------------------------
extern "C" void kernel_launch(void* const* d_in, const int* in_sizes, int n_in,
                              void* d_out, int out_size) {
    const float* x      = (const float*)d_in[0];
    const float* rw     = (const float*)d_in[1];
    const float* bias   = (const float*)d_in[2];
    const float* gate_w = (const float*)d_in[3];
    const float* up_w   = (const float*)d_in[4];
    const float* down_w = (const float*)d_in[5];
    const float* sgw    = (const float*)d_in[6];
    const float* suw    = (const float*)d_in[7];
    const float* sdw    = (const float*)d_in[8];
    float* out = (float*)d_out;

    int *counts, *elist, *tok_e, *tok_pos;
    float *wlist;
    __half *xh, *gate_h, *up_h, *down_h, *sgw_h, *suw_h, *sdw_h, *hidden_h, *hs_h, *dout_h;
    cudaGetSymbolAddress((void**)&counts, g_counts);
    cudaGetSymbolAddress((void**)&elist, g_elist);
    cudaGetSymbolAddress((void**)&wlist, g_wlist);
    cudaGetSymbolAddress((void**)&tok_e, g_tok_e);
    cudaGetSymbolAddress((void**)&tok_pos, g_tok_pos);
    cudaGetSymbolAddress((void**)&dout_h, g_dout_h);
    cudaGetSymbolAddress((void**)&xh, g_xh);
    cudaGetSymbolAddress((void**)&gate_h, g_gate_h);
    cudaGetSymbolAddress((void**)&up_h, g_up_h);
    cudaGetSymbolAddress((void**)&down_h, g_down_h);
    cudaGetSymbolAddress((void**)&sgw_h, g_sgw_h);
    cudaGetSymbolAddress((void**)&suw_h, g_suw_h);
    cudaGetSymbolAddress((void**)&sdw_h, g_sdw_h);
    cudaGetSymbolAddress((void**)&hidden_h, g_hidden_h);
    cudaGetSymbolAddress((void**)&hs_h, g_hs_h);

    cudaFuncSetAttribute(gateup_all, cudaFuncAttributeMaxDynamicSharedMemorySize, GU_SMEM);
    cudaFuncSetAttribute(down_all, cudaFuncAttributeMaxDynamicSharedMemorySize, DN_SMEM);

    cudaMemsetAsync(counts, 0, E_NUM * sizeof(int));

    // One merged prep launch (cvt + transposes + router)
    prep_kernel<<<16640, 256>>>(x, sgw, suw, sdw, gate_w, up_w, down_w, rw, bias,
                                xh, sgw_h, suw_h, sdw_h, gate_h, up_h, down_h,
                                counts, elist, wlist, tok_e, tok_pos);

    // Merged gate/up (routed 512 slots + shared 256 tiles)
    gateup_all<<<768, 512, GU_SMEM>>>(xh, gate_h, up_h, sgw_h, suw_h,
                                      hidden_h, hs_h, counts, elist, wlist);

    // Merged down (routed 2048 slots + shared 128 tiles)
    down_all<<<2176, 512, DN_SMEM>>>(hidden_h, down_h, hs_h, sdw_h, dout_h, out, counts);

    // Combine routed rows into out
    combine_kernel<<<S_TOK, 256>>>(tok_e, tok_pos, dout_h, out);
}

// round 8
// speedup vs baseline: 2.3290x; 1.1701x over previous
#include <cuda_runtime.h>
#include <cuda_fp16.h>
#include <math.h>
#include <stdint.h>

// Problem constants
#define S_TOK 2048
#define C_DIM 1024
#define E_NUM 16
#define H_DIM 256
#define HS_DIM 2048
#define CAP   2048

// ---------------------------------------------------------------------------
// Device scratch
// ---------------------------------------------------------------------------
__device__ int    g_counts[E_NUM];
__device__ int    g_elist[E_NUM * CAP];
__device__ float  g_wlist[E_NUM * CAP];
__device__ int    g_tok_e[S_TOK * 4];
__device__ int    g_tok_pos[S_TOK * 4];
__device__ __half g_dout_h[(size_t)E_NUM * CAP * C_DIM];
__device__ __half g_xh[(size_t)S_TOK * C_DIM];
__device__ __half g_gate_h[(size_t)E_NUM * H_DIM * C_DIM];   // [e][H][C] K-major
__device__ __half g_up_h[(size_t)E_NUM * H_DIM * C_DIM];
__device__ __half g_down_h[(size_t)E_NUM * C_DIM * H_DIM];   // [e][C][H] K-major
__device__ __half g_sgw_h[(size_t)HS_DIM * C_DIM];
__device__ __half g_suw_h[(size_t)HS_DIM * C_DIM];
__device__ __half g_sdw_h[(size_t)C_DIM * HS_DIM];
__device__ __half g_hidden_h[(size_t)E_NUM * CAP * H_DIM];
__device__ __half g_hs_h[(size_t)S_TOK * HS_DIM];

// ---------------------------------------------------------------------------
// Helpers
// ---------------------------------------------------------------------------
__device__ __forceinline__ uint32_t smem_u32(const void* p) {
    uint32_t a;
    asm("{ .reg .u64 t; cvta.to.shared.u64 t, %1; cvt.u32.u64 %0, t; }" : "=r"(a) : "l"(p));
    return a;
}
__device__ __forceinline__ void cpasync16(uint32_t dst, const void* src) {
    asm volatile("cp.async.cg.shared.global [%0], [%1], 16;" :: "r"(dst), "l"(src));
}
#define CP_COMMIT() asm volatile("cp.async.commit_group;" ::: "memory")
#define CP_WAIT1()  asm volatile("cp.async.wait_group 1;" ::: "memory")
#define CP_WAIT0()  asm volatile("cp.async.wait_group 0;" ::: "memory")
__device__ __forceinline__ void ldsm4(uint32_t* r, uint32_t a) {
    asm volatile("ldmatrix.sync.aligned.m8n8.x4.shared.b16 {%0,%1,%2,%3}, [%4];"
                 : "=r"(r[0]), "=r"(r[1]), "=r"(r[2]), "=r"(r[3]) : "r"(a));
}
__device__ __forceinline__ void mma16(float* d, const uint32_t* a, const uint32_t* b) {
    asm volatile(
        "mma.sync.aligned.m16n8k16.row.col.f32.f16.f16.f32 "
        "{%0,%1,%2,%3}, {%4,%5,%6,%7}, {%8,%9}, {%0,%1,%2,%3};"
        : "+f"(d[0]), "+f"(d[1]), "+f"(d[2]), "+f"(d[3])
        : "r"(a[0]), "r"(a[1]), "r"(a[2]), "r"(a[3]), "r"(b[0]), "r"(b[1]));
}
// swizzled byte offset inside one (rows x 32 halves) stage (row stride 64B)
#define SWZ(row, seg) ((uint32_t)((row) * 64 + ((((seg) ^ ((row) >> 1)) & 3) << 4)))

// ---------------------------------------------------------------------------
// Merged prep: fp16 conversions, weight transposes, router — ONE launch.
// ---------------------------------------------------------------------------
__global__ __launch_bounds__(256)
void prep_kernel(const float* __restrict__ x, const float* __restrict__ sgw,
                 const float* __restrict__ suw, const float* __restrict__ sdw,
                 const float* __restrict__ gate_w, const float* __restrict__ up_w,
                 const float* __restrict__ down_w,
                 const float* __restrict__ rw, const float* __restrict__ bias,
                 __half* __restrict__ xh, __half* __restrict__ sgw_h,
                 __half* __restrict__ suw_h, __half* __restrict__ sdw_h,
                 __half* __restrict__ gate_h, __half* __restrict__ up_h,
                 __half* __restrict__ down_h,
                 int* __restrict__ counts, int* __restrict__ elist,
                 float* __restrict__ wlist, int* __restrict__ tok_e,
                 int* __restrict__ tok_pos) {
    int b = blockIdx.x;
    int tid = threadIdx.x;

    if (b < 4096) {
        const float* src;
        __half* dst;
        int lb;
        if (b < 1024)      { src = x;   dst = xh;    lb = b; }
        else if (b < 2048) { src = sgw; dst = sgw_h; lb = b - 1024; }
        else if (b < 3072) { src = suw; dst = suw_h; lb = b - 2048; }
        else               { src = sdw; dst = sdw_h; lb = b - 3072; }
        int i = (lb * 256 + tid) * 8;
        float4 a = *(const float4*)(src + i);
        float4 c = *(const float4*)(src + i + 4);
        __half2 h[4];
        h[0] = __floats2half2_rn(a.x, a.y);
        h[1] = __floats2half2_rn(a.z, a.w);
        h[2] = __floats2half2_rn(c.x, c.y);
        h[3] = __floats2half2_rn(c.z, c.w);
        *(uint4*)(dst + i) = *(uint4*)h;
    } else if (b < 16384) {
        __shared__ float t[32][33];
        int tt = b - 4096;
        const float* in;
        __half* outp;
        int R, C, bx, by, bz;
        if (tt < 4096) {
            in = gate_w; outp = gate_h; R = C_DIM; C = H_DIM;
            bz = tt >> 8; int r = tt & 255; by = r >> 3; bx = r & 7;
        } else if (tt < 8192) {
            tt -= 4096;
            in = up_w; outp = up_h; R = C_DIM; C = H_DIM;
            bz = tt >> 8; int r = tt & 255; by = r >> 3; bx = r & 7;
        } else {
            tt -= 8192;
            in = down_w; outp = down_h; R = H_DIM; C = C_DIM;
            bz = tt >> 8; int r = tt & 255; by = r >> 5; bx = r & 31;
        }
        in += (size_t)bz * R * C;
        outp += (size_t)bz * R * C;
        int c0 = bx * 32, r0 = by * 32;
        int tx = tid & 31, ty = tid >> 5;
#pragma unroll
        for (int j = 0; j < 32; j += 8)
            t[ty + j][tx] = in[(size_t)(r0 + ty + j) * C + c0 + tx];
        __syncthreads();
#pragma unroll
        for (int j = 0; j < 32; j += 8)
            outp[(size_t)(c0 + ty + j) * R + r0 + tx] = __float2half_rn(t[tx][ty + j]);
    } else {
        int warp_id = (b - 16384) * 8 + (tid >> 5);
        int lane = tid & 31;
        if (warp_id >= S_TOK) return;
        const float* xr = x + (size_t)warp_id * C_DIM;
        float logits[E_NUM];
#pragma unroll
        for (int e = 0; e < E_NUM; e++) {
            const float* wr = rw + (size_t)e * C_DIM;
            float p = 0.f;
            for (int c = lane; c < C_DIM; c += 32) p = fmaf(xr[c], wr[c], p);
#pragma unroll
            for (int off = 16; off; off >>= 1) p += __shfl_xor_sync(0xffffffffu, p, off);
            logits[e] = p;
        }
        if (lane == 0) {
            float sc[E_NUM], sb[E_NUM];
#pragma unroll
            for (int e = 0; e < E_NUM; e++) {
                sc[e] = 1.f / (1.f + expf(-logits[e]));
                sb[e] = sc[e] + bias[e];
            }
            float gsc[4];
#pragma unroll
            for (int g = 0; g < 4; g++) {
                float m1 = -1e30f, m2 = -1e30f;
#pragma unroll
                for (int j = 0; j < 4; j++) {
                    float v = sb[g * 4 + j];
                    if (v > m1) { m2 = m1; m1 = v; } else if (v > m2) m2 = v;
                }
                gsc[g] = m1 + m2;
            }
            int bg0 = 0;
            for (int g = 1; g < 4; g++) if (gsc[g] > gsc[bg0]) bg0 = g;
            int bg1 = -1;
            for (int g = 0; g < 4; g++) {
                if (g == bg0) continue;
                if (bg1 < 0 || gsc[g] > gsc[bg1]) bg1 = g;
            }
            bool allowed[E_NUM];
#pragma unroll
            for (int e = 0; e < E_NUM; e++) {
                int g = e >> 2;
                allowed[e] = (g == bg0) || (g == bg1);
            }
            int idx[4];
            for (int k = 0; k < 4; k++) {
                int bi = 0; float bv = -1e30f;
                for (int e = 0; e < E_NUM; e++)
                    if (allowed[e] && sb[e] > bv) { bv = sb[e]; bi = e; }
                allowed[bi] = false;
                idx[k] = bi;
            }
            float wsum = 1e-20f;
            for (int k = 0; k < 4; k++) wsum += sc[idx[k]];
            for (int k = 0; k < 4; k++) {
                int e = idx[k];
                int pos = atomicAdd(&counts[e], 1);
                elist[e * CAP + pos] = warp_id;
                wlist[e * CAP + pos] = sc[e] / wsum;
                tok_e[warp_id * 4 + k] = e;
                tok_pos[warp_id * 4 + k] = pos;
            }
        }
    }
}

// ---------------------------------------------------------------------------
// fp16 gate/up dual GEMM + SiLU. 256 threads, tile 128x64, 2 CTAs/SM.
// cp.async 3-stage. Warp grid 4(m) x 2(n), warp tile 32x32 (dual).
// Stage: A 8KB @0, G 4KB @8192, U 4KB @12288 (16KB/stage, 3 stages = 48KB).
// ---------------------------------------------------------------------------
#define GU_SMEM 49152

__global__ __launch_bounds__(256, 2)
void gateup_all(const __half* __restrict__ xh,
                const __half* __restrict__ gate_h, const __half* __restrict__ up_h,
                const __half* __restrict__ sgw_h, const __half* __restrict__ suw_h,
                __half* __restrict__ hidden_h, __half* __restrict__ hs_h,
                const int* __restrict__ counts, const int* __restrict__ elist,
                const float* __restrict__ wlist) {
    extern __shared__ __align__(16) char sm[];
    const int Kd = C_DIM;
    const int NCH = Kd / 32;

    int bid = blockIdx.x;
    bool routed = bid < 1024;
    int e = 0, cnt = 0, m0, n0;
    const __half* Bg;
    const __half* Bu;
    if (routed) {
        e = bid >> 6;
        int r = bid & 63;
        m0 = (r >> 2) * 128;
        n0 = (r & 3) * 64;
        cnt = counts[e];
        if (m0 >= cnt) return;
        Bg = gate_h + (size_t)e * H_DIM * C_DIM;
        Bu = up_h + (size_t)e * H_DIM * C_DIM;
    } else {
        int t = bid - 1024;
        n0 = (t & 31) * 64;
        m0 = (t >> 5) * 128;
        Bg = sgw_h;
        Bu = suw_h;
    }

    int tid = threadIdx.x, wid = tid >> 5, lane = tid & 31;
    int grp = lane >> 2, thr = lane & 3;
    int wm = (wid & 3) * 32, wn = (wid >> 2) * 32;   // 4m x 2n

    // loader: A rows lrow & lrow+64 (2 cp), B rows lrow (1 cp each of g,u)
    int lrow = tid >> 2, lseg = tid & 3;
    int atok0, atok1;
    if (routed) {
        int i0 = m0 + lrow, i1 = m0 + lrow + 64;
        atok0 = elist[e * CAP + (i0 < cnt ? i0 : 0)];
        atok1 = elist[e * CAP + (i1 < cnt ? i1 : 0)];
    } else {
        atok0 = m0 + lrow;
        atok1 = m0 + lrow + 64;
    }
    const __half* aptr0 = xh + (size_t)atok0 * Kd + lseg * 8;
    const __half* aptr1 = xh + (size_t)atok1 * Kd + lseg * 8;
    const __half* gptr = Bg + (size_t)(n0 + lrow) * Kd + lseg * 8;
    const __half* uptr = Bu + (size_t)(n0 + lrow) * Kd + lseg * 8;

    uint32_t base = smem_u32(sm);
    uint32_t soA0 = SWZ(lrow, lseg), soA1 = SWZ(lrow + 64, lseg);
    uint32_t soB = SWZ(lrow, lseg);

    int q = lane >> 3;
    int rA0 = wm + (q & 1) * 8 + (lane & 7);
    int sAadd = q >> 1;
    int rB0 = wn + (q >> 1) * 8 + (lane & 7);
    int sBadd = q & 1;

    float accg[2][4][4], accu[2][4][4];
#pragma unroll
    for (int i = 0; i < 2; i++)
#pragma unroll
        for (int j = 0; j < 4; j++)
#pragma unroll
            for (int v = 0; v < 4; v++) { accg[i][j][v] = 0.f; accu[i][j][v] = 0.f; }

    // prologue: chunks 0,1
#pragma unroll
    for (int p = 0; p < 2; p++) {
        uint32_t sb0 = base + p * 16384;
        int k0 = p * 32;
        cpasync16(sb0 + soA0, aptr0 + k0);
        cpasync16(sb0 + soA1, aptr1 + k0);
        cpasync16(sb0 + 8192 + soB, gptr + k0);
        cpasync16(sb0 + 12288 + soB, uptr + k0);
        CP_COMMIT();
    }

    for (int i = 0; i < NCH; i++) {
        if (i + 1 < NCH) CP_WAIT1(); else CP_WAIT0();
        __syncthreads();
        if (i + 2 < NCH) {
            int s = (i + 2) % 3;
            uint32_t sb0 = base + s * 16384;
            int k0 = (i + 2) * 32;
            cpasync16(sb0 + soA0, aptr0 + k0);
            cpasync16(sb0 + soA1, aptr1 + k0);
            cpasync16(sb0 + 8192 + soB, gptr + k0);
            cpasync16(sb0 + 12288 + soB, uptr + k0);
            CP_COMMIT();
        }
        uint32_t ab = base + (i % 3) * 16384;
        uint32_t gb = ab + 8192;
        uint32_t ub = ab + 12288;
#pragma unroll
        for (int ks = 0; ks < 2; ks++) {
            int s0 = ks * 2;
            uint32_t af[2][4], bgt[2][4], but[2][4];
            ldsm4(af[0], ab + SWZ(rA0, s0 + sAadd));
            ldsm4(af[1], ab + SWZ(rA0 + 16, s0 + sAadd));
            ldsm4(bgt[0], gb + SWZ(rB0, s0 + sBadd));
            ldsm4(bgt[1], gb + SWZ(rB0 + 16, s0 + sBadd));
            ldsm4(but[0], ub + SWZ(rB0, s0 + sBadd));
            ldsm4(but[1], ub + SWZ(rB0 + 16, s0 + sBadd));
#pragma unroll
            for (int mi = 0; mi < 2; mi++)
#pragma unroll
                for (int jj = 0; jj < 4; jj++) {
                    mma16(accg[mi][jj], af[mi], &bgt[jj >> 1][(jj & 1) * 2]);
                    mma16(accu[mi][jj], af[mi], &but[jj >> 1][(jj & 1) * 2]);
                }
        }
    }

    // epilogue: silu(g)*u*scale -> fp16
#pragma unroll
    for (int mi = 0; mi < 2; mi++) {
#pragma unroll
        for (int half = 0; half < 2; half++) {
            int gidx = m0 + wm + mi * 16 + grp + half * 8;
            float scale = 1.f;
            __half* orow = nullptr;
            bool valid = true;
            if (routed) {
                valid = gidx < cnt;
                if (valid) {
                    scale = wlist[e * CAP + gidx];
                    orow = hidden_h + ((size_t)e * CAP + gidx) * H_DIM + n0;
                }
            } else {
                orow = hs_h + (size_t)gidx * HS_DIM + n0;
            }
            if (valid) {
#pragma unroll
                for (int j = 0; j < 4; j++) {
                    int c = wn + j * 8 + thr * 2;
                    float g0 = accg[mi][j][half * 2], g1 = accg[mi][j][half * 2 + 1];
                    float u0 = accu[mi][j][half * 2], u1 = accu[mi][j][half * 2 + 1];
                    float o0 = (g0 / (1.f + expf(-g0))) * u0 * scale;
                    float o1 = (g1 / (1.f + expf(-g1))) * u1 * scale;
                    *(__half2*)(orow + c) = __floats2half2_rn(o0, o1);
                }
            }
        }
    }
}

// ---------------------------------------------------------------------------
// fp16 down GEMM. 256 threads, tile 128x64, 2 CTAs/SM. cp.async 3-stage.
// Stage: A 8KB @0, B 4KB @8192 (12KB/stage, 3 stages = 36KB).
// ---------------------------------------------------------------------------
#define DN_SMEM 36864

__global__ __launch_bounds__(256, 2)
void down_all(const __half* __restrict__ hidden_h, const __half* __restrict__ down_h,
              const __half* __restrict__ hs_h, const __half* __restrict__ sdw_h,
              __half* __restrict__ dout_h, float* __restrict__ out,
              const int* __restrict__ counts) {
    extern __shared__ __align__(16) char sm[];

    int bid = blockIdx.x;
    bool routed = bid < 4096;
    int e = 0, cnt = 0, m0, n0, Kd;
    const __half* A;
    const __half* B;
    if (routed) {
        e = bid >> 8;
        int r = bid & 255;
        m0 = (r >> 4) * 128;
        n0 = (r & 15) * 64;
        cnt = counts[e];
        if (m0 >= cnt) return;
        A = hidden_h + (size_t)e * CAP * H_DIM;
        B = down_h + (size_t)e * C_DIM * H_DIM;
        Kd = H_DIM;
    } else {
        int t = bid - 4096;
        m0 = (t >> 4) * 128;
        n0 = (t & 15) * 64;
        A = hs_h;
        B = sdw_h;
        Kd = HS_DIM;
    }
    const int NCH = Kd / 32;

    int tid = threadIdx.x, wid = tid >> 5, lane = tid & 31;
    int grp = lane >> 2, thr = lane & 3;
    int wm = (wid & 3) * 32, wn = (wid >> 2) * 32;

    int lrow = tid >> 2, lseg = tid & 3;
    const __half* aptr0 = A + (size_t)(m0 + lrow) * Kd + lseg * 8;
    const __half* aptr1 = A + (size_t)(m0 + lrow + 64) * Kd + lseg * 8;
    const __half* bptr = B + (size_t)(n0 + lrow) * Kd + lseg * 8;

    uint32_t base = smem_u32(sm);
    uint32_t soA0 = SWZ(lrow, lseg), soA1 = SWZ(lrow + 64, lseg);
    uint32_t soB = SWZ(lrow, lseg);

    int q = lane >> 3;
    int rA0 = wm + (q & 1) * 8 + (lane & 7);
    int sAadd = q >> 1;
    int rB0 = wn + (q >> 1) * 8 + (lane & 7);
    int sBadd = q & 1;

    float acc[2][4][4];
#pragma unroll
    for (int i = 0; i < 2; i++)
#pragma unroll
        for (int j = 0; j < 4; j++)
#pragma unroll
            for (int v = 0; v < 4; v++) acc[i][j][v] = 0.f;

#pragma unroll
    for (int p = 0; p < 2; p++) {
        if (p < NCH) {
            uint32_t sb0 = base + p * 12288;
            int k0 = p * 32;
            cpasync16(sb0 + soA0, aptr0 + k0);
            cpasync16(sb0 + soA1, aptr1 + k0);
            cpasync16(sb0 + 8192 + soB, bptr + k0);
        }
        CP_COMMIT();
    }

    for (int i = 0; i < NCH; i++) {
        if (i + 1 < NCH) CP_WAIT1(); else CP_WAIT0();
        __syncthreads();
        if (i + 2 < NCH) {
            int s = (i + 2) % 3;
            uint32_t sb0 = base + s * 12288;
            int k0 = (i + 2) * 32;
            cpasync16(sb0 + soA0, aptr0 + k0);
            cpasync16(sb0 + soA1, aptr1 + k0);
            cpasync16(sb0 + 8192 + soB, bptr + k0);
            CP_COMMIT();
        }
        uint32_t ab = base + (i % 3) * 12288;
        uint32_t bb = ab + 8192;
#pragma unroll
        for (int ks = 0; ks < 2; ks++) {
            int s0 = ks * 2;
            uint32_t af[2][4], bft[2][4];
            ldsm4(af[0], ab + SWZ(rA0, s0 + sAadd));
            ldsm4(af[1], ab + SWZ(rA0 + 16, s0 + sAadd));
            ldsm4(bft[0], bb + SWZ(rB0, s0 + sBadd));
            ldsm4(bft[1], bb + SWZ(rB0 + 16, s0 + sBadd));
#pragma unroll
            for (int mi = 0; mi < 2; mi++)
#pragma unroll
                for (int jj = 0; jj < 4; jj++)
                    mma16(acc[mi][jj], af[mi], &bft[jj >> 1][(jj & 1) * 2]);
        }
    }

#pragma unroll
    for (int mi = 0; mi < 2; mi++) {
#pragma unroll
        for (int half = 0; half < 2; half++) {
            int gidx = m0 + wm + mi * 16 + grp + half * 8;
            if (routed) {
                if (gidx < cnt) {
                    __half* orow = dout_h + ((size_t)e * CAP + gidx) * C_DIM + n0;
#pragma unroll
                    for (int j = 0; j < 4; j++) {
                        int c = wn + j * 8 + thr * 2;
                        *(__half2*)(orow + c) = __floats2half2_rn(acc[mi][j][half * 2],
                                                                  acc[mi][j][half * 2 + 1]);
                    }
                }
            } else {
                float* orow = out + (size_t)gidx * C_DIM + n0;
#pragma unroll
                for (int j = 0; j < 4; j++) {
                    int c = wn + j * 8 + thr * 2;
                    float2 o;
                    o.x = acc[mi][j][half * 2];
                    o.y = acc[mi][j][half * 2 + 1];
                    *(float2*)(orow + c) = o;
                }
            }
        }
    }
}

// ---------------------------------------------------------------------------
// Final combine: out[s] += sum_k dout_h[e_k][pos_k]
// ---------------------------------------------------------------------------
__global__ void combine_kernel(const int* __restrict__ tok_e,
                               const int* __restrict__ tok_pos,
                               const __half* __restrict__ dout_h,
                               float* __restrict__ out) {
    int s = blockIdx.x;
    int c = threadIdx.x * 4;
    float4 acc = *(const float4*)(out + (size_t)s * C_DIM + c);
#pragma unroll
    for (int k = 0; k < 4; k++) {
        int e = tok_e[s * 4 + k];
        int p = tok_pos[s * 4 + k];
        const __half* row = dout_h + ((size_t)e * CAP + p) * C_DIM + c;
        uint2 raw = *(const uint2*)row;
        __half2 h0 = *(__half2*)&raw.x;
        __half2 h1 = *(__half2*)&raw.y;
        float2 f0 = __half22float2(h0);
        float2 f1 = __half22float2(h1);
        acc.x += f0.x; acc.y += f0.y; acc.z += f1.x; acc.w += f1.y;
    }
    *(float4*)(out + (size_t)s * C_DIM + c) = acc;
}

// ---------------------------------------------------------------------------
// Launch
// ---------------------------------------------------------------------------
extern "C" void kernel_launch(void* const* d_in, const int* in_sizes, int n_in,
                              void* d_out, int out_size) {
    const float* x      = (const float*)d_in[0];
    const float* rw     = (const float*)d_in[1];
    const float* bias   = (const float*)d_in[2];
    const float* gate_w = (const float*)d_in[3];
    const float* up_w   = (const float*)d_in[4];
    const float* down_w = (const float*)d_in[5];
    const float* sgw    = (const float*)d_in[6];
    const float* suw    = (const float*)d_in[7];
    const float* sdw    = (const float*)d_in[8];
    float* out = (float*)d_out;

    int *counts, *elist, *tok_e, *tok_pos;
    float *wlist;
    __half *xh, *gate_h, *up_h, *down_h, *sgw_h, *suw_h, *sdw_h, *hidden_h, *hs_h, *dout_h;
    cudaGetSymbolAddress((void**)&counts, g_counts);
    cudaGetSymbolAddress((void**)&elist, g_elist);
    cudaGetSymbolAddress((void**)&wlist, g_wlist);
    cudaGetSymbolAddress((void**)&tok_e, g_tok_e);
    cudaGetSymbolAddress((void**)&tok_pos, g_tok_pos);
    cudaGetSymbolAddress((void**)&dout_h, g_dout_h);
    cudaGetSymbolAddress((void**)&xh, g_xh);
    cudaGetSymbolAddress((void**)&gate_h, g_gate_h);
    cudaGetSymbolAddress((void**)&up_h, g_up_h);
    cudaGetSymbolAddress((void**)&down_h, g_down_h);
    cudaGetSymbolAddress((void**)&sgw_h, g_sgw_h);
    cudaGetSymbolAddress((void**)&suw_h, g_suw_h);
    cudaGetSymbolAddress((void**)&sdw_h, g_sdw_h);
    cudaGetSymbolAddress((void**)&hidden_h, g_hidden_h);
    cudaGetSymbolAddress((void**)&hs_h, g_hs_h);

    cudaFuncSetAttribute(gateup_all, cudaFuncAttributeMaxDynamicSharedMemorySize, GU_SMEM);
    cudaFuncSetAttribute(down_all, cudaFuncAttributeMaxDynamicSharedMemorySize, DN_SMEM);

    cudaMemsetAsync(counts, 0, E_NUM * sizeof(int));

    // One merged prep launch (cvt + transposes + router)
    prep_kernel<<<16640, 256>>>(x, sgw, suw, sdw, gate_w, up_w, down_w, rw, bias,
                                xh, sgw_h, suw_h, sdw_h, gate_h, up_h, down_h,
                                counts, elist, wlist, tok_e, tok_pos);

    // Merged gate/up: routed 1024 slots + shared 512 tiles (128x64 tiles)
    gateup_all<<<1536, 256, GU_SMEM>>>(xh, gate_h, up_h, sgw_h, suw_h,
                                       hidden_h, hs_h, counts, elist, wlist);

    // Merged down: routed 4096 slots + shared 256 tiles (128x64 tiles)
    down_all<<<4352, 256, DN_SMEM>>>(hidden_h, down_h, hs_h, sdw_h, dout_h, out, counts);

    // Combine routed rows into out
    combine_kernel<<<S_TOK, 256>>>(tok_e, tok_pos, dout_h, out);
}

// round 9
// speedup vs baseline: 2.4166x; 1.0376x over previous
#include <cuda_runtime.h>
#include <cuda_fp16.h>
#include <math.h>
#include <stdint.h>

// Problem constants
#define S_TOK 2048
#define C_DIM 1024
#define E_NUM 16
#define H_DIM 256
#define HS_DIM 2048
#define CAP   2048

// ---------------------------------------------------------------------------
// Device scratch
// ---------------------------------------------------------------------------
__device__ int    g_counts[E_NUM];
__device__ int    g_elist[E_NUM * CAP];
__device__ float  g_wlist[E_NUM * CAP];
__device__ int    g_tok_e[S_TOK * 4];
__device__ int    g_tok_pos[S_TOK * 4];
__device__ __half g_dout_h[(size_t)E_NUM * CAP * C_DIM];
__device__ __half g_xh[(size_t)S_TOK * C_DIM];
__device__ __half g_gate_h[(size_t)E_NUM * H_DIM * C_DIM];   // [e][H][C] K-major
__device__ __half g_up_h[(size_t)E_NUM * H_DIM * C_DIM];
__device__ __half g_down_h[(size_t)E_NUM * C_DIM * H_DIM];   // [e][C][H] K-major
__device__ __half g_sgw_h[(size_t)HS_DIM * C_DIM];
__device__ __half g_suw_h[(size_t)HS_DIM * C_DIM];
__device__ __half g_sdw_h[(size_t)C_DIM * HS_DIM];
__device__ __half g_hidden_h[(size_t)E_NUM * CAP * H_DIM];
__device__ __half g_hs_h[(size_t)S_TOK * HS_DIM];

// ---------------------------------------------------------------------------
// Helpers
// ---------------------------------------------------------------------------
__device__ __forceinline__ uint32_t smem_u32(const void* p) {
    uint32_t a;
    asm("{ .reg .u64 t; cvta.to.shared.u64 t, %1; cvt.u32.u64 %0, t; }" : "=r"(a) : "l"(p));
    return a;
}
__device__ __forceinline__ void cpasync16(uint32_t dst, const void* src) {
    asm volatile("cp.async.cg.shared.global [%0], [%1], 16;" :: "r"(dst), "l"(src));
}
#define CP_COMMIT() asm volatile("cp.async.commit_group;" ::: "memory")
#define CP_WAIT1()  asm volatile("cp.async.wait_group 1;" ::: "memory")
#define CP_WAIT0()  asm volatile("cp.async.wait_group 0;" ::: "memory")
__device__ __forceinline__ void ldsm4(uint32_t* r, uint32_t a) {
    asm volatile("ldmatrix.sync.aligned.m8n8.x4.shared.b16 {%0,%1,%2,%3}, [%4];"
                 : "=r"(r[0]), "=r"(r[1]), "=r"(r[2]), "=r"(r[3]) : "r"(a));
}
__device__ __forceinline__ void mma16(float* d, const uint32_t* a, const uint32_t* b) {
    asm volatile(
        "mma.sync.aligned.m16n8k16.row.col.f32.f16.f16.f32 "
        "{%0,%1,%2,%3}, {%4,%5,%6,%7}, {%8,%9}, {%0,%1,%2,%3};"
        : "+f"(d[0]), "+f"(d[1]), "+f"(d[2]), "+f"(d[3])
        : "r"(a[0]), "r"(a[1]), "r"(a[2]), "r"(a[3]), "r"(b[0]), "r"(b[1]));
}
// swizzled byte offset inside one (rows x 32 halves) stage (row stride 64B)
#define SWZ(row, seg) ((uint32_t)((row) * 64 + ((((seg) ^ ((row) >> 1)) & 3) << 4)))

// shared building blocks for prep work (used from two kernels)
__device__ __forceinline__ void do_cvt_block(const float* __restrict__ src,
                                             __half* __restrict__ dst,
                                             int lb, int tid) {
    int i = (lb * 256 + tid) * 8;
    float4 a = *(const float4*)(src + i);
    float4 c = *(const float4*)(src + i + 4);
    __half2 h[4];
    h[0] = __floats2half2_rn(a.x, a.y);
    h[1] = __floats2half2_rn(a.z, a.w);
    h[2] = __floats2half2_rn(c.x, c.y);
    h[3] = __floats2half2_rn(c.z, c.w);
    *(uint4*)(dst + i) = *(uint4*)h;
}

// ---------------------------------------------------------------------------
// Prep A: cvt x/sgw/suw, transpose gate/up, router.
// blocks [0,3072): cvt; [3072,11264): transpose; [11264,11520): router
// ---------------------------------------------------------------------------
__global__ __launch_bounds__(256)
void prep_kernel(const float* __restrict__ x, const float* __restrict__ sgw,
                 const float* __restrict__ suw,
                 const float* __restrict__ gate_w, const float* __restrict__ up_w,
                 const float* __restrict__ rw, const float* __restrict__ bias,
                 __half* __restrict__ xh, __half* __restrict__ sgw_h,
                 __half* __restrict__ suw_h,
                 __half* __restrict__ gate_h, __half* __restrict__ up_h,
                 int* __restrict__ counts, int* __restrict__ elist,
                 float* __restrict__ wlist, int* __restrict__ tok_e,
                 int* __restrict__ tok_pos) {
    int b = blockIdx.x;
    int tid = threadIdx.x;

    if (b < 3072) {
        const float* src;
        __half* dst;
        int lb;
        if (b < 1024)      { src = x;   dst = xh;    lb = b; }
        else if (b < 2048) { src = sgw; dst = sgw_h; lb = b - 1024; }
        else               { src = suw; dst = suw_h; lb = b - 2048; }
        do_cvt_block(src, dst, lb, tid);
    } else if (b < 11264) {
        __shared__ float t[32][33];
        int tt = b - 3072;
        const float* in;
        __half* outp;
        if (tt < 4096) { in = gate_w; outp = gate_h; }
        else           { in = up_w;   outp = up_h; tt -= 4096; }
        const int R = C_DIM, C = H_DIM;
        int bz = tt >> 8;
        int r = tt & 255;
        int by = r >> 3, bx = r & 7;
        in += (size_t)bz * R * C;
        outp += (size_t)bz * R * C;
        int c0 = bx * 32, r0 = by * 32;
        int tx = tid & 31, ty = tid >> 5;
#pragma unroll
        for (int j = 0; j < 32; j += 8)
            t[ty + j][tx] = in[(size_t)(r0 + ty + j) * C + c0 + tx];
        __syncthreads();
#pragma unroll
        for (int j = 0; j < 32; j += 8)
            outp[(size_t)(c0 + ty + j) * R + r0 + tx] = __float2half_rn(t[tx][ty + j]);
    } else {
        int warp_id = (b - 11264) * 8 + (tid >> 5);
        int lane = tid & 31;
        if (warp_id >= S_TOK) return;
        const float* xr = x + (size_t)warp_id * C_DIM;
        float logits[E_NUM];
#pragma unroll
        for (int e = 0; e < E_NUM; e++) {
            const float* wr = rw + (size_t)e * C_DIM;
            float p = 0.f;
            for (int c = lane; c < C_DIM; c += 32) p = fmaf(xr[c], wr[c], p);
#pragma unroll
            for (int off = 16; off; off >>= 1) p += __shfl_xor_sync(0xffffffffu, p, off);
            logits[e] = p;
        }
        if (lane == 0) {
            float sc[E_NUM], sb[E_NUM];
#pragma unroll
            for (int e = 0; e < E_NUM; e++) {
                sc[e] = 1.f / (1.f + expf(-logits[e]));
                sb[e] = sc[e] + bias[e];
            }
            float gsc[4];
#pragma unroll
            for (int g = 0; g < 4; g++) {
                float m1 = -1e30f, m2 = -1e30f;
#pragma unroll
                for (int j = 0; j < 4; j++) {
                    float v = sb[g * 4 + j];
                    if (v > m1) { m2 = m1; m1 = v; } else if (v > m2) m2 = v;
                }
                gsc[g] = m1 + m2;
            }
            int bg0 = 0;
            for (int g = 1; g < 4; g++) if (gsc[g] > gsc[bg0]) bg0 = g;
            int bg1 = -1;
            for (int g = 0; g < 4; g++) {
                if (g == bg0) continue;
                if (bg1 < 0 || gsc[g] > gsc[bg1]) bg1 = g;
            }
            bool allowed[E_NUM];
#pragma unroll
            for (int e = 0; e < E_NUM; e++) {
                int g = e >> 2;
                allowed[e] = (g == bg0) || (g == bg1);
            }
            int idx[4];
            for (int k = 0; k < 4; k++) {
                int bi = 0; float bv = -1e30f;
                for (int e = 0; e < E_NUM; e++)
                    if (allowed[e] && sb[e] > bv) { bv = sb[e]; bi = e; }
                allowed[bi] = false;
                idx[k] = bi;
            }
            float wsum = 1e-20f;
            for (int k = 0; k < 4; k++) wsum += sc[idx[k]];
            for (int k = 0; k < 4; k++) {
                int e = idx[k];
                int pos = atomicAdd(&counts[e], 1);
                elist[e * CAP + pos] = warp_id;
                wlist[e * CAP + pos] = sc[e] / wsum;
                tok_e[warp_id * 4 + k] = e;
                tok_pos[warp_id * 4 + k] = pos;
            }
        }
    }
}

// ---------------------------------------------------------------------------
// gateup_all: fp16 dual GEMM + SiLU (bids [0,1536)) PLUS overlapped down-weight
// prep (bids [1536,2560): sdw cvt; [2560,6656): down transpose). The prep
// blocks run in gateup's spare slots; down_all launches after, so ordering OK.
// GEMM: 256 thr, tile 128x64, 2 CTAs/SM, cp.async 3-stage.
// ---------------------------------------------------------------------------
#define GU_SMEM 49152

__global__ __launch_bounds__(256, 2)
void gateup_all(const __half* __restrict__ xh,
                const __half* __restrict__ gate_h, const __half* __restrict__ up_h,
                const __half* __restrict__ sgw_h, const __half* __restrict__ suw_h,
                __half* __restrict__ hidden_h, __half* __restrict__ hs_h,
                const int* __restrict__ counts, const int* __restrict__ elist,
                const float* __restrict__ wlist,
                const float* __restrict__ sdw, __half* __restrict__ sdw_h,
                const float* __restrict__ down_w, __half* __restrict__ down_h) {
    extern __shared__ __align__(16) char sm[];
    int bid = blockIdx.x;
    int tid = threadIdx.x;

    if (bid >= 1536) {
        if (bid < 2560) {
            // sdw fp32 -> fp16 flat cvt
            do_cvt_block(sdw, sdw_h, bid - 1536, tid);
        } else {
            // down_w transpose+cvt: [e][H][C] -> [e][C][H]
            __shared__ float t[32][33];
            int tt = bid - 2560;
            const int R = H_DIM, C = C_DIM;
            int bz = tt >> 8;
            int r = tt & 255;
            int by = r >> 5, bx = r & 31;
            const float* in = down_w + (size_t)bz * R * C;
            __half* outp = down_h + (size_t)bz * R * C;
            int c0 = bx * 32, r0 = by * 32;
            int tx = tid & 31, ty = tid >> 5;
#pragma unroll
            for (int j = 0; j < 32; j += 8)
                t[ty + j][tx] = in[(size_t)(r0 + ty + j) * C + c0 + tx];
            __syncthreads();
#pragma unroll
            for (int j = 0; j < 32; j += 8)
                outp[(size_t)(c0 + ty + j) * R + r0 + tx] = __float2half_rn(t[tx][ty + j]);
        }
        return;
    }

    const int Kd = C_DIM;
    const int NCH = Kd / 32;

    bool routed = bid < 1024;
    int e = 0, cnt = 0, m0, n0;
    const __half* Bg;
    const __half* Bu;
    if (routed) {
        e = bid >> 6;
        int r = bid & 63;
        m0 = (r >> 2) * 128;
        n0 = (r & 3) * 64;
        cnt = counts[e];
        if (m0 >= cnt) return;
        Bg = gate_h + (size_t)e * H_DIM * C_DIM;
        Bu = up_h + (size_t)e * H_DIM * C_DIM;
    } else {
        int t = bid - 1024;
        n0 = (t & 31) * 64;
        m0 = (t >> 5) * 128;
        Bg = sgw_h;
        Bu = suw_h;
    }

    int wid = tid >> 5, lane = tid & 31;
    int grp = lane >> 2, thr = lane & 3;
    int wm = (wid & 3) * 32, wn = (wid >> 2) * 32;   // 4m x 2n

    int lrow = tid >> 2, lseg = tid & 3;
    int atok0, atok1;
    if (routed) {
        int i0 = m0 + lrow, i1 = m0 + lrow + 64;
        atok0 = elist[e * CAP + (i0 < cnt ? i0 : 0)];
        atok1 = elist[e * CAP + (i1 < cnt ? i1 : 0)];
    } else {
        atok0 = m0 + lrow;
        atok1 = m0 + lrow + 64;
    }
    const __half* aptr0 = xh + (size_t)atok0 * Kd + lseg * 8;
    const __half* aptr1 = xh + (size_t)atok1 * Kd + lseg * 8;
    const __half* gptr = Bg + (size_t)(n0 + lrow) * Kd + lseg * 8;
    const __half* uptr = Bu + (size_t)(n0 + lrow) * Kd + lseg * 8;

    uint32_t base = smem_u32(sm);
    uint32_t soA0 = SWZ(lrow, lseg), soA1 = SWZ(lrow + 64, lseg);
    uint32_t soB = SWZ(lrow, lseg);

    int q = lane >> 3;
    int rA0 = wm + (q & 1) * 8 + (lane & 7);
    int sAadd = q >> 1;
    int rB0 = wn + (q >> 1) * 8 + (lane & 7);
    int sBadd = q & 1;

    float accg[2][4][4], accu[2][4][4];
#pragma unroll
    for (int i = 0; i < 2; i++)
#pragma unroll
        for (int j = 0; j < 4; j++)
#pragma unroll
            for (int v = 0; v < 4; v++) { accg[i][j][v] = 0.f; accu[i][j][v] = 0.f; }

#pragma unroll
    for (int p = 0; p < 2; p++) {
        uint32_t sb0 = base + p * 16384;
        int k0 = p * 32;
        cpasync16(sb0 + soA0, aptr0 + k0);
        cpasync16(sb0 + soA1, aptr1 + k0);
        cpasync16(sb0 + 8192 + soB, gptr + k0);
        cpasync16(sb0 + 12288 + soB, uptr + k0);
        CP_COMMIT();
    }

    for (int i = 0; i < NCH; i++) {
        if (i + 1 < NCH) CP_WAIT1(); else CP_WAIT0();
        __syncthreads();
        if (i + 2 < NCH) {
            int s = (i + 2) % 3;
            uint32_t sb0 = base + s * 16384;
            int k0 = (i + 2) * 32;
            cpasync16(sb0 + soA0, aptr0 + k0);
            cpasync16(sb0 + soA1, aptr1 + k0);
            cpasync16(sb0 + 8192 + soB, gptr + k0);
            cpasync16(sb0 + 12288 + soB, uptr + k0);
            CP_COMMIT();
        }
        uint32_t ab = base + (i % 3) * 16384;
        uint32_t gb = ab + 8192;
        uint32_t ub = ab + 12288;
#pragma unroll
        for (int ks = 0; ks < 2; ks++) {
            int s0 = ks * 2;
            uint32_t af[2][4], bgt[2][4], but[2][4];
            ldsm4(af[0], ab + SWZ(rA0, s0 + sAadd));
            ldsm4(af[1], ab + SWZ(rA0 + 16, s0 + sAadd));
            ldsm4(bgt[0], gb + SWZ(rB0, s0 + sBadd));
            ldsm4(bgt[1], gb + SWZ(rB0 + 16, s0 + sBadd));
            ldsm4(but[0], ub + SWZ(rB0, s0 + sBadd));
            ldsm4(but[1], ub + SWZ(rB0 + 16, s0 + sBadd));
#pragma unroll
            for (int mi = 0; mi < 2; mi++)
#pragma unroll
                for (int jj = 0; jj < 4; jj++) {
                    mma16(accg[mi][jj], af[mi], &bgt[jj >> 1][(jj & 1) * 2]);
                    mma16(accu[mi][jj], af[mi], &but[jj >> 1][(jj & 1) * 2]);
                }
        }
    }

#pragma unroll
    for (int mi = 0; mi < 2; mi++) {
#pragma unroll
        for (int half = 0; half < 2; half++) {
            int gidx = m0 + wm + mi * 16 + grp + half * 8;
            float scale = 1.f;
            __half* orow = nullptr;
            bool valid = true;
            if (routed) {
                valid = gidx < cnt;
                if (valid) {
                    scale = wlist[e * CAP + gidx];
                    orow = hidden_h + ((size_t)e * CAP + gidx) * H_DIM + n0;
                }
            } else {
                orow = hs_h + (size_t)gidx * HS_DIM + n0;
            }
            if (valid) {
#pragma unroll
                for (int j = 0; j < 4; j++) {
                    int c = wn + j * 8 + thr * 2;
                    float g0 = accg[mi][j][half * 2], g1 = accg[mi][j][half * 2 + 1];
                    float u0 = accu[mi][j][half * 2], u1 = accu[mi][j][half * 2 + 1];
                    float o0 = (g0 / (1.f + expf(-g0))) * u0 * scale;
                    float o1 = (g1 / (1.f + expf(-g1))) * u1 * scale;
                    *(__half2*)(orow + c) = __floats2half2_rn(o0, o1);
                }
            }
        }
    }
}

// ---------------------------------------------------------------------------
// fp16 down GEMM. Shared tiles FIRST (long K=2048 CTAs start at t=0), routed
// after. 256 thr, tile 128x64, 2 CTAs/SM, cp.async 3-stage.
// ---------------------------------------------------------------------------
#define DN_SMEM 36864

__global__ __launch_bounds__(256, 2)
void down_all(const __half* __restrict__ hidden_h, const __half* __restrict__ down_h,
              const __half* __restrict__ hs_h, const __half* __restrict__ sdw_h,
              __half* __restrict__ dout_h, float* __restrict__ out,
              const int* __restrict__ counts) {
    extern __shared__ __align__(16) char sm[];

    int bid = blockIdx.x;
    bool routed = bid >= 256;
    int e = 0, cnt = 0, m0, n0, Kd;
    const __half* A;
    const __half* B;
    if (routed) {
        int r2 = bid - 256;
        e = r2 >> 8;
        int r = r2 & 255;
        m0 = (r >> 4) * 128;
        n0 = (r & 15) * 64;
        cnt = counts[e];
        if (m0 >= cnt) return;
        A = hidden_h + (size_t)e * CAP * H_DIM;
        B = down_h + (size_t)e * C_DIM * H_DIM;
        Kd = H_DIM;
    } else {
        m0 = (bid >> 4) * 128;
        n0 = (bid & 15) * 64;
        A = hs_h;
        B = sdw_h;
        Kd = HS_DIM;
    }
    const int NCH = Kd / 32;

    int tid = threadIdx.x, wid = tid >> 5, lane = tid & 31;
    int grp = lane >> 2, thr = lane & 3;
    int wm = (wid & 3) * 32, wn = (wid >> 2) * 32;

    int lrow = tid >> 2, lseg = tid & 3;
    const __half* aptr0 = A + (size_t)(m0 + lrow) * Kd + lseg * 8;
    const __half* aptr1 = A + (size_t)(m0 + lrow + 64) * Kd + lseg * 8;
    const __half* bptr = B + (size_t)(n0 + lrow) * Kd + lseg * 8;

    uint32_t base = smem_u32(sm);
    uint32_t soA0 = SWZ(lrow, lseg), soA1 = SWZ(lrow + 64, lseg);
    uint32_t soB = SWZ(lrow, lseg);

    int q = lane >> 3;
    int rA0 = wm + (q & 1) * 8 + (lane & 7);
    int sAadd = q >> 1;
    int rB0 = wn + (q >> 1) * 8 + (lane & 7);
    int sBadd = q & 1;

    float acc[2][4][4];
#pragma unroll
    for (int i = 0; i < 2; i++)
#pragma unroll
        for (int j = 0; j < 4; j++)
#pragma unroll
            for (int v = 0; v < 4; v++) acc[i][j][v] = 0.f;

#pragma unroll
    for (int p = 0; p < 2; p++) {
        if (p < NCH) {
            uint32_t sb0 = base + p * 12288;
            int k0 = p * 32;
            cpasync16(sb0 + soA0, aptr0 + k0);
            cpasync16(sb0 + soA1, aptr1 + k0);
            cpasync16(sb0 + 8192 + soB, bptr + k0);
        }
        CP_COMMIT();
    }

    for (int i = 0; i < NCH; i++) {
        if (i + 1 < NCH) CP_WAIT1(); else CP_WAIT0();
        __syncthreads();
        if (i + 2 < NCH) {
            int s = (i + 2) % 3;
            uint32_t sb0 = base + s * 12288;
            int k0 = (i + 2) * 32;
            cpasync16(sb0 + soA0, aptr0 + k0);
            cpasync16(sb0 + soA1, aptr1 + k0);
            cpasync16(sb0 + 8192 + soB, bptr + k0);
            CP_COMMIT();
        }
        uint32_t ab = base + (i % 3) * 12288;
        uint32_t bb = ab + 8192;
#pragma unroll
        for (int ks = 0; ks < 2; ks++) {
            int s0 = ks * 2;
            uint32_t af[2][4], bft[2][4];
            ldsm4(af[0], ab + SWZ(rA0, s0 + sAadd));
            ldsm4(af[1], ab + SWZ(rA0 + 16, s0 + sAadd));
            ldsm4(bft[0], bb + SWZ(rB0, s0 + sBadd));
            ldsm4(bft[1], bb + SWZ(rB0 + 16, s0 + sBadd));
#pragma unroll
            for (int mi = 0; mi < 2; mi++)
#pragma unroll
                for (int jj = 0; jj < 4; jj++)
                    mma16(acc[mi][jj], af[mi], &bft[jj >> 1][(jj & 1) * 2]);
        }
    }

#pragma unroll
    for (int mi = 0; mi < 2; mi++) {
#pragma unroll
        for (int half = 0; half < 2; half++) {
            int gidx = m0 + wm + mi * 16 + grp + half * 8;
            if (routed) {
                if (gidx < cnt) {
                    __half* orow = dout_h + ((size_t)e * CAP + gidx) * C_DIM + n0;
#pragma unroll
                    for (int j = 0; j < 4; j++) {
                        int c = wn + j * 8 + thr * 2;
                        *(__half2*)(orow + c) = __floats2half2_rn(acc[mi][j][half * 2],
                                                                  acc[mi][j][half * 2 + 1]);
                    }
                }
            } else {
                float* orow = out + (size_t)gidx * C_DIM + n0;
#pragma unroll
                for (int j = 0; j < 4; j++) {
                    int c = wn + j * 8 + thr * 2;
                    float2 o;
                    o.x = acc[mi][j][half * 2];
                    o.y = acc[mi][j][half * 2 + 1];
                    *(float2*)(orow + c) = o;
                }
            }
        }
    }
}

// ---------------------------------------------------------------------------
// Final combine: out[s] += sum_k dout_h[e_k][pos_k]
// ---------------------------------------------------------------------------
__global__ void combine_kernel(const int* __restrict__ tok_e,
                               const int* __restrict__ tok_pos,
                               const __half* __restrict__ dout_h,
                               float* __restrict__ out) {
    int s = blockIdx.x;
    int c = threadIdx.x * 4;
    float4 acc = *(const float4*)(out + (size_t)s * C_DIM + c);
#pragma unroll
    for (int k = 0; k < 4; k++) {
        int e = tok_e[s * 4 + k];
        int p = tok_pos[s * 4 + k];
        const __half* row = dout_h + ((size_t)e * CAP + p) * C_DIM + c;
        uint2 raw = *(const uint2*)row;
        __half2 h0 = *(__half2*)&raw.x;
        __half2 h1 = *(__half2*)&raw.y;
        float2 f0 = __half22float2(h0);
        float2 f1 = __half22float2(h1);
        acc.x += f0.x; acc.y += f0.y; acc.z += f1.x; acc.w += f1.y;
    }
    *(float4*)(out + (size_t)s * C_DIM + c) = acc;
}

// ---------------------------------------------------------------------------
// Launch
// ---------------------------------------------------------------------------
extern "C" void kernel_launch(void* const* d_in, const int* in_sizes, int n_in,
                              void* d_out, int out_size) {
    const float* x      = (const float*)d_in[0];
    const float* rw     = (const float*)d_in[1];
    const float* bias   = (const float*)d_in[2];
    const float* gate_w = (const float*)d_in[3];
    const float* up_w   = (const float*)d_in[4];
    const float* down_w = (const float*)d_in[5];
    const float* sgw    = (const float*)d_in[6];
    const float* suw    = (const float*)d_in[7];
    const float* sdw    = (const float*)d_in[8];
    float* out = (float*)d_out;

    int *counts, *elist, *tok_e, *tok_pos;
    float *wlist;
    __half *xh, *gate_h, *up_h, *down_h, *sgw_h, *suw_h, *sdw_h, *hidden_h, *hs_h, *dout_h;
    cudaGetSymbolAddress((void**)&counts, g_counts);
    cudaGetSymbolAddress((void**)&elist, g_elist);
    cudaGetSymbolAddress((void**)&wlist, g_wlist);
    cudaGetSymbolAddress((void**)&tok_e, g_tok_e);
    cudaGetSymbolAddress((void**)&tok_pos, g_tok_pos);
    cudaGetSymbolAddress((void**)&dout_h, g_dout_h);
    cudaGetSymbolAddress((void**)&xh, g_xh);
    cudaGetSymbolAddress((void**)&gate_h, g_gate_h);
    cudaGetSymbolAddress((void**)&up_h, g_up_h);
    cudaGetSymbolAddress((void**)&down_h, g_down_h);
    cudaGetSymbolAddress((void**)&sgw_h, g_sgw_h);
    cudaGetSymbolAddress((void**)&suw_h, g_suw_h);
    cudaGetSymbolAddress((void**)&sdw_h, g_sdw_h);
    cudaGetSymbolAddress((void**)&hidden_h, g_hidden_h);
    cudaGetSymbolAddress((void**)&hs_h, g_hs_h);

    cudaFuncSetAttribute(gateup_all, cudaFuncAttributeMaxDynamicSharedMemorySize, GU_SMEM);
    cudaFuncSetAttribute(down_all, cudaFuncAttributeMaxDynamicSharedMemorySize, DN_SMEM);

    cudaMemsetAsync(counts, 0, E_NUM * sizeof(int));

    // Prep A: x/sgw/suw cvt + gate/up transpose + router
    prep_kernel<<<11520, 256>>>(x, sgw, suw, gate_w, up_w, rw, bias,
                                xh, sgw_h, suw_h, gate_h, up_h,
                                counts, elist, wlist, tok_e, tok_pos);

    // gateup GEMM (1536 blocks) + overlapped down-weight prep (5120 blocks)
    gateup_all<<<6656, 256, GU_SMEM>>>(xh, gate_h, up_h, sgw_h, suw_h,
                                       hidden_h, hs_h, counts, elist, wlist,
                                       sdw, sdw_h, down_w, down_h);

    // down GEMM: shared-first (256) + routed (4096)
    down_all<<<4352, 256, DN_SMEM>>>(hidden_h, down_h, hs_h, sdw_h, dout_h, out, counts);

    // Combine routed rows into out
    combine_kernel<<<S_TOK, 256>>>(tok_e, tok_pos, dout_h, out);
}